// round 1
// baseline (speedup 1.0000x reference)
#include <cuda_runtime.h>
#include <math.h>
#include <stdint.h>

// Problem constants
#define BB   4
#define SS   2048
#define DD   1024
#define HH   16
#define HD   64
#define FF   4096
#define NR   (BB*SS)          // 8192 rows
#define EPSL 1e-5f

// ---------------- scratch (device globals; no allocation allowed) ----------
__device__ float g_q [NR*DD];
__device__ float g_k [NR*DD];
__device__ float g_v [NR*DD];
__device__ float g_a [NR*DD];
__device__ float g_r [NR*DD];
__device__ float g_ff[(size_t)NR*FF];

// ---------------- SGEMM: C[M,N] = A[M,K] @ B[K,N] (+bias)(+relu) ----------
// BM=BN=128, BK=8, 256 threads, 8x8 per-thread microtile.
// EPI: 0 = plain, 1 = +bias +relu, 2 = +bias
template<int EPI>
__global__ __launch_bounds__(256)
void sgemm_kernel(int M, int N, int K,
                  const float* __restrict__ A,
                  const float* __restrict__ B,
                  const float* __restrict__ bias,
                  float* __restrict__ C)
{
    const int BM = 128, BN = 128, BK = 8;
    __shared__ float As[BK][BM];
    __shared__ float Bs[BK][BN];

    int tid  = threadIdx.x;
    int row0 = blockIdx.y * BM;
    int col0 = blockIdx.x * BN;

    // A tile loader: each thread one float4 (128 rows x 8 cols)
    int aRow = tid >> 1;
    int aCol = (tid & 1) * 4;
    // B tile loader: each thread one float4 (8 rows x 128 cols)
    int bRow = tid >> 5;
    int bCol = (tid & 31) * 4;

    const float* Aptr = A + (size_t)(row0 + aRow) * K + aCol;
    const float* Bptr = B + (size_t)bRow * N + col0 + bCol;

    int tx = tid & 15;   // column group
    int ty = tid >> 4;   // row group

    float acc[8][8];
    #pragma unroll
    for (int i = 0; i < 8; i++)
        #pragma unroll
        for (int j = 0; j < 8; j++) acc[i][j] = 0.f;

    for (int kt = 0; kt < K; kt += BK) {
        float4 av = *(const float4*)Aptr;
        float4 bv = *(const float4*)Bptr;
        As[aCol + 0][aRow] = av.x;
        As[aCol + 1][aRow] = av.y;
        As[aCol + 2][aRow] = av.z;
        As[aCol + 3][aRow] = av.w;
        *(float4*)&Bs[bRow][bCol] = bv;
        __syncthreads();

        #pragma unroll
        for (int k = 0; k < BK; k++) {
            float ar[8], br[8];
            #pragma unroll
            for (int i = 0; i < 8; i++) ar[i] = As[k][ty * 8 + i];
            #pragma unroll
            for (int j = 0; j < 8; j++) br[j] = Bs[k][tx * 8 + j];
            #pragma unroll
            for (int i = 0; i < 8; i++)
                #pragma unroll
                for (int j = 0; j < 8; j++)
                    acc[i][j] += ar[i] * br[j];
        }
        __syncthreads();
        Aptr += BK;
        Bptr += (size_t)BK * N;
    }

    // epilogue: vectorized float4 stores
    #pragma unroll
    for (int i = 0; i < 8; i++) {
        size_t r = row0 + ty * 8 + i;
        float* Crow = C + r * N + col0 + tx * 8;
        #pragma unroll
        for (int j4 = 0; j4 < 8; j4 += 4) {
            float4 ov;
            float vv[4];
            #pragma unroll
            for (int jj = 0; jj < 4; jj++) {
                float v = acc[i][j4 + jj];
                if (EPI >= 1) v += bias[col0 + tx * 8 + j4 + jj];
                if (EPI == 1) v = fmaxf(v, 0.f);
                vv[jj] = v;
            }
            ov.x = vv[0]; ov.y = vv[1]; ov.z = vv[2]; ov.w = vv[3];
            *(float4*)(Crow + j4) = ov;
        }
    }
}

// ---------------- flash attention -----------------------------------------
// grid: (S/64, B*H). block 256 threads. 64-query x 64-key tiles, online
// softmax. Keys >= valid_len are exactly zero-weight in the reference
// (exp(-1e6 - m) underflows), so the key loop stops at ceil(vl/64).
__global__ __launch_bounds__(256)
void attn_kernel(const float* __restrict__ Q,
                 const float* __restrict__ K,
                 const float* __restrict__ V,
                 const int*   __restrict__ vlen,
                 float* __restrict__ O)
{
    extern __shared__ float sm[];
    const int P = 65;                     // pad to kill bank conflicts
    float* Qs = sm;                       // [64][65]
    float* Ks = Qs + 64 * P;
    float* Vs = Ks + 64 * P;
    float* Ps = Vs + 64 * P;

    int tid = threadIdx.x;
    int bh  = blockIdx.y;
    int b   = bh >> 4;
    int h   = bh & 15;
    int q0  = blockIdx.x * 64;
    int vl  = vlen[b];

    const float* Qb = Q + (size_t)(b * SS) * DD + h * HD;
    const float* Kb = K + (size_t)(b * SS) * DD + h * HD;
    const float* Vb = V + (size_t)(b * SS) * DD + h * HD;

    // load Q tile (64 rows x 64 cols), 4 float4 per thread
    #pragma unroll
    for (int it = 0; it < 4; it++) {
        int idx = tid + it * 256;
        int r = idx >> 4;
        int c = (idx & 15) * 4;
        float4 vq = *(const float4*)(Qb + (size_t)(q0 + r) * DD + c);
        Qs[r * P + c + 0] = vq.x;
        Qs[r * P + c + 1] = vq.y;
        Qs[r * P + c + 2] = vq.z;
        Qs[r * P + c + 3] = vq.w;
    }

    int tx = tid & 15, ty = tid >> 4;
    int qr = ty * 4;          // local query rows [qr, qr+3]
    int dc = tx * 4;          // local cols (keys in phase 1, dims in phase 2)

    float m_i[4], l_i[4], o[4][4];
    #pragma unroll
    for (int i = 0; i < 4; i++) {
        m_i[i] = -1e30f;
        l_i[i] = 0.f;
        #pragma unroll
        for (int j = 0; j < 4; j++) o[i][j] = 0.f;
    }

    int nkt = (vl + 63) >> 6;
    for (int kt = 0; kt < nkt; kt++) {
        int k0 = kt * 64;
        __syncthreads();   // previous PV reads done before overwriting K/V
        // load K & V tiles
        #pragma unroll
        for (int it = 0; it < 4; it++) {
            int idx = tid + it * 256;
            int r = idx >> 4;
            int c = (idx & 15) * 4;
            float4 vk = *(const float4*)(Kb + (size_t)(k0 + r) * DD + c);
            float4 vv = *(const float4*)(Vb + (size_t)(k0 + r) * DD + c);
            Ks[r * P + c + 0] = vk.x; Ks[r * P + c + 1] = vk.y;
            Ks[r * P + c + 2] = vk.z; Ks[r * P + c + 3] = vk.w;
            Vs[r * P + c + 0] = vv.x; Vs[r * P + c + 1] = vv.y;
            Vs[r * P + c + 2] = vv.z; Vs[r * P + c + 3] = vv.w;
        }
        __syncthreads();

        // scores: s[i][j] = sum_d Qs[qr+i][d] * Ks[dc+j][d]
        float s[4][4];
        #pragma unroll
        for (int i = 0; i < 4; i++)
            #pragma unroll
            for (int j = 0; j < 4; j++) s[i][j] = 0.f;
        #pragma unroll 8
        for (int d = 0; d < 64; d++) {
            float ar[4], br[4];
            #pragma unroll
            for (int i = 0; i < 4; i++) ar[i] = Qs[(qr + i) * P + d];
            #pragma unroll
            for (int j = 0; j < 4; j++) br[j] = Ks[(dc + j) * P + d];
            #pragma unroll
            for (int i = 0; i < 4; i++)
                #pragma unroll
                for (int j = 0; j < 4; j++)
                    s[i][j] += ar[i] * br[j];
        }
        // scale + mask
        #pragma unroll
        for (int i = 0; i < 4; i++)
            #pragma unroll
            for (int j = 0; j < 4; j++) {
                float v = s[i][j] * 0.125f;     // 1/sqrt(64)
                int kg = k0 + dc + j;
                s[i][j] = (kg < vl) ? v : -1e30f;
            }
        // online softmax update (rows owned by 16-lane groups)
        #pragma unroll
        for (int i = 0; i < 4; i++) {
            float rm = fmaxf(fmaxf(s[i][0], s[i][1]), fmaxf(s[i][2], s[i][3]));
            #pragma unroll
            for (int off = 8; off >= 1; off >>= 1)
                rm = fmaxf(rm, __shfl_xor_sync(0xffffffffu, rm, off));
            float mn = fmaxf(m_i[i], rm);
            float al = __expf(m_i[i] - mn);
            float rs = 0.f;
            #pragma unroll
            for (int j = 0; j < 4; j++) {
                float p = __expf(s[i][j] - mn);
                Ps[(qr + i) * P + dc + j] = p;
                rs += p;
            }
            #pragma unroll
            for (int off = 8; off >= 1; off >>= 1)
                rs += __shfl_xor_sync(0xffffffffu, rs, off);
            l_i[i] = l_i[i] * al + rs;
            m_i[i] = mn;
            #pragma unroll
            for (int j = 0; j < 4; j++) o[i][j] *= al;
        }
        __syncthreads();

        // PV: o[i][j] += sum_k Ps[qr+i][k] * Vs[k][dc+j]
        #pragma unroll 8
        for (int k = 0; k < 64; k++) {
            float pa[4], vb[4];
            #pragma unroll
            for (int i = 0; i < 4; i++) pa[i] = Ps[(qr + i) * P + k];
            #pragma unroll
            for (int j = 0; j < 4; j++) vb[j] = Vs[k * P + dc + j];
            #pragma unroll
            for (int i = 0; i < 4; i++)
                #pragma unroll
                for (int j = 0; j < 4; j++)
                    o[i][j] += pa[i] * vb[j];
        }
    }

    float* Ob = O + (size_t)(b * SS) * DD + h * HD;
    #pragma unroll
    for (int i = 0; i < 4; i++) {
        float inv = 1.f / l_i[i];
        #pragma unroll
        for (int j = 0; j < 4; j++)
            Ob[(size_t)(q0 + qr + i) * DD + dc + j] = o[i][j] * inv;
    }
}

// ---------------- fused residual + LayerNorm -------------------------------
// one block per row (D=1024, 256 threads x 4 elems)
__global__ __launch_bounds__(256)
void ln_kernel(const float* __restrict__ A,
               const float* __restrict__ R,
               const float* __restrict__ g,
               const float* __restrict__ be,
               float* __restrict__ out)
{
    int row = blockIdx.x;
    int t   = threadIdx.x;
    const float4* a4 = (const float4*)(A + (size_t)row * DD);
    const float4* r4 = (const float4*)(R + (size_t)row * DD);
    float4 av = a4[t];
    float4 rv = r4[t];
    float x0 = av.x + rv.x, x1 = av.y + rv.y, x2 = av.z + rv.z, x3 = av.w + rv.w;

    float s = x0 + x1 + x2 + x3;
    float q = x0 * x0 + x1 * x1 + x2 * x2 + x3 * x3;
    #pragma unroll
    for (int off = 16; off >= 1; off >>= 1) {
        s += __shfl_xor_sync(0xffffffffu, s, off);
        q += __shfl_xor_sync(0xffffffffu, q, off);
    }
    __shared__ float rs[8], rq[8];
    int w = t >> 5, lane = t & 31;
    if (lane == 0) { rs[w] = s; rq[w] = q; }
    __syncthreads();
    float tot = 0.f, totq = 0.f;
    #pragma unroll
    for (int i = 0; i < 8; i++) { tot += rs[i]; totq += rq[i]; }

    float mean = tot * (1.f / DD);
    float var  = totq * (1.f / DD) - mean * mean;
    float rstd = rsqrtf(var + EPSL);

    float4 gv = ((const float4*)g)[t];
    float4 bv = ((const float4*)be)[t];
    float4 ov;
    ov.x = (x0 - mean) * rstd * gv.x + bv.x;
    ov.y = (x1 - mean) * rstd * gv.y + bv.y;
    ov.z = (x2 - mean) * rstd * gv.z + bv.z;
    ov.w = (x3 - mean) * rstd * gv.w + bv.w;
    ((float4*)(out + (size_t)row * DD))[t] = ov;
}

// ---------------- launch ----------------------------------------------------
extern "C" void kernel_launch(void* const* d_in, const int* in_sizes, int n_in,
                              void* d_out, int out_size)
{
    const float* x   = (const float*)d_in[0];
    const int*   vl  = (const int*)  d_in[1];
    const float* Wq  = (const float*)d_in[2];
    const float* Wk  = (const float*)d_in[3];
    const float* Wv  = (const float*)d_in[4];
    const float* Wo  = (const float*)d_in[5];
    const float* W1  = (const float*)d_in[6];
    const float* b1  = (const float*)d_in[7];
    const float* W2  = (const float*)d_in[8];
    const float* b2  = (const float*)d_in[9];
    const float* g1  = (const float*)d_in[10];
    const float* be1 = (const float*)d_in[11];
    const float* g2  = (const float*)d_in[12];
    const float* be2 = (const float*)d_in[13];
    float* out = (float*)d_out;

    float *q, *k, *v, *a, *r, *ff;
    cudaGetSymbolAddress((void**)&q,  g_q);
    cudaGetSymbolAddress((void**)&k,  g_k);
    cudaGetSymbolAddress((void**)&v,  g_v);
    cudaGetSymbolAddress((void**)&a,  g_a);
    cudaGetSymbolAddress((void**)&r,  g_r);
    cudaGetSymbolAddress((void**)&ff, g_ff);

    int attn_smem = 4 * 64 * 65 * (int)sizeof(float);   // 66560 B
    cudaFuncSetAttribute(attn_kernel,
                         cudaFuncAttributeMaxDynamicSharedMemorySize, attn_smem);

    dim3 gD(DD / 128, NR / 128);     // (8, 64)
    dim3 gF(FF / 128, NR / 128);     // (32, 64)

    // QKV projections
    sgemm_kernel<0><<<gD, 256>>>(NR, DD, DD, x, Wq, nullptr, q);
    sgemm_kernel<0><<<gD, 256>>>(NR, DD, DD, x, Wk, nullptr, k);
    sgemm_kernel<0><<<gD, 256>>>(NR, DD, DD, x, Wv, nullptr, v);

    // attention
    attn_kernel<<<dim3(SS / 64, BB * HH), 256, attn_smem>>>(q, k, v, vl, a);

    // output projection (reuse q as attn_out)
    sgemm_kernel<0><<<gD, 256>>>(NR, DD, DD, a, Wo, nullptr, q);

    // residual + LN1 -> r
    ln_kernel<<<NR, 256>>>(q, x, g1, be1, r);

    // FFN
    sgemm_kernel<1><<<gF, 256>>>(NR, FF, DD, r, W1, b1, ff);   // +b1, relu
    sgemm_kernel<2><<<gD, 256>>>(NR, DD, FF, ff, W2, b2, k);   // +b2 (reuse k)

    // residual + LN2 -> output
    ln_kernel<<<NR, 256>>>(k, r, g2, be2, out);
}

// round 3
// speedup vs baseline: 1.9009x; 1.9009x over previous
#include <cuda_runtime.h>
#include <cuda_bf16.h>
#include <math.h>
#include <stdint.h>

// Problem constants
#define BB   4
#define SS   2048
#define DD   1024
#define HH   16
#define HD   64
#define FF   4096
#define NR   (BB*SS)          // 8192 rows
#define EPSL 1e-5f

// ---------------- scratch (device globals; no allocation allowed) ----------
__device__ float g_q [NR*DD];
__device__ float g_k [NR*DD];
__device__ float g_v [NR*DD];
__device__ float g_a [NR*DD];
__device__ float g_r [NR*DD];
__device__ float g_ff[(size_t)NR*FF];

// ---------------- tensor-core GEMM (3xBF16 split) ---------------------------
// C[M,N] = A[M,K] @ B[K,N] (+bias)(+relu), fp32 in/out, internally bf16 split:
// a = a_hi + a_lo, b = b_hi + b_lo;  acc += a_hi*b_hi + a_hi*b_lo + a_lo*b_hi
// (lo*lo term ~2^-32 relative, negligible). Effective precision ~1e-5.
// BM=128, BN=128, BK=32, 256 threads (8 warps, 2x4), warp tile 64x32.

#define LDSM_X4(R0,R1,R2,R3,ADDR) \
    asm volatile("ldmatrix.sync.aligned.m8n8.x4.shared.b16 {%0,%1,%2,%3},[%4];" \
        : "=r"(R0),"=r"(R1),"=r"(R2),"=r"(R3) : "r"(ADDR))

#define LDSM_X4_T(R0,R1,R2,R3,ADDR) \
    asm volatile("ldmatrix.sync.aligned.m8n8.x4.trans.shared.b16 {%0,%1,%2,%3},[%4];" \
        : "=r"(R0),"=r"(R1),"=r"(R2),"=r"(R3) : "r"(ADDR))

#define MMA16816(D,A0,A1,A2,A3,B0,B1) \
    asm volatile("mma.sync.aligned.m16n8k16.row.col.f32.bf16.bf16.f32 " \
        "{%0,%1,%2,%3},{%4,%5,%6,%7},{%8,%9},{%0,%1,%2,%3};" \
        : "+f"(D[0]),"+f"(D[1]),"+f"(D[2]),"+f"(D[3]) \
        : "r"(A0),"r"(A1),"r"(A2),"r"(A3),"r"(B0),"r"(B1))

template<int EPI>   // 0 plain, 1 +bias+relu, 2 +bias
__global__ __launch_bounds__(256, 1)
void hgemm_kernel(int M, int N, int K,
                  const float* __restrict__ A,
                  const float* __restrict__ B,
                  const float* __restrict__ bias,
                  float* __restrict__ C)
{
    const int BK = 32;
    const int PA = 40;     // A smem pitch (halves): 80B rows, conflict-free
    const int PB = 136;    // B smem pitch (halves): 272B rows, conflict-free

    __shared__ __align__(16) __nv_bfloat16 As_hi[128 * PA];
    __shared__ __align__(16) __nv_bfloat16 As_lo[128 * PA];
    __shared__ __align__(16) __nv_bfloat16 Bs_hi[32 * PB];
    __shared__ __align__(16) __nv_bfloat16 Bs_lo[32 * PB];

    int tid  = threadIdx.x;
    int lane = tid & 31;
    int warp = tid >> 5;
    int wm = warp & 1;            // 2 warps along M  -> warp tile 64 rows
    int wn = warp >> 1;           // 4 warps along N  -> warp tile 32 cols
    int row0 = blockIdx.y * 128;
    int col0 = blockIdx.x * 128;

    float acc[4][4][4];
    #pragma unroll
    for (int i = 0; i < 4; i++)
        #pragma unroll
        for (int j = 0; j < 4; j++)
            #pragma unroll
            for (int c = 0; c < 4; c++) acc[i][j][c] = 0.f;

    // prefetch registers: 4 float4 for A tile, 4 float4 for B tile
    float4 pa[4], pb[4];

    // loader geometry:
    //  A tile 128x32 fp32 = 1024 float4: idx -> r=idx>>3 (0..127), c4=idx&7
    //  B tile 32x128 fp32 = 1024 float4: idx -> r=idx>>5 (0..31), c4=idx&31

    #pragma unroll
    for (int it = 0; it < 4; it++) {
        int idx = it * 256 + tid;
        pa[it] = *(const float4*)(A + (size_t)(row0 + (idx >> 3)) * K + (idx & 7) * 4);
        pb[it] = *(const float4*)(B + (size_t)(idx >> 5) * N + col0 + (idx & 31) * 4);
    }

    for (int kt = 0; kt < K; kt += BK) {
        // split + store to smem
        #pragma unroll
        for (int it = 0; it < 4; it++) {
            int idx = it * 256 + tid;
            {
                int r = idx >> 3, c = (idx & 7) * 4;
                float vv[4] = {pa[it].x, pa[it].y, pa[it].z, pa[it].w};
                #pragma unroll
                for (int j = 0; j < 4; j++) {
                    __nv_bfloat16 h = __float2bfloat16(vv[j]);
                    As_hi[r * PA + c + j] = h;
                    As_lo[r * PA + c + j] = __float2bfloat16(vv[j] - __bfloat162float(h));
                }
            }
            {
                int r = idx >> 5, c = (idx & 31) * 4;
                float vv[4] = {pb[it].x, pb[it].y, pb[it].z, pb[it].w};
                #pragma unroll
                for (int j = 0; j < 4; j++) {
                    __nv_bfloat16 h = __float2bfloat16(vv[j]);
                    Bs_hi[r * PB + c + j] = h;
                    Bs_lo[r * PB + c + j] = __float2bfloat16(vv[j] - __bfloat162float(h));
                }
            }
        }
        __syncthreads();

        // prefetch next tile
        if (kt + BK < K) {
            #pragma unroll
            for (int it = 0; it < 4; it++) {
                int idx = it * 256 + tid;
                pa[it] = *(const float4*)(A + (size_t)(row0 + (idx >> 3)) * K + kt + BK + (idx & 7) * 4);
                pb[it] = *(const float4*)(B + (size_t)(kt + BK + (idx >> 5)) * N + col0 + (idx & 31) * 4);
            }
        }

        // compute: two k16 steps
        #pragma unroll
        for (int kk = 0; kk < BK; kk += 16) {
            uint32_t ahi[4][4], alo[4][4], bhi[4][2], blo[4][2];

            #pragma unroll
            for (int mi = 0; mi < 4; mi++) {
                int r = wm * 64 + mi * 16 + (lane & 15);
                int c = kk + (lane >> 4) * 8;
                uint32_t ah = (uint32_t)__cvta_generic_to_shared(&As_hi[r * PA + c]);
                uint32_t al = (uint32_t)__cvta_generic_to_shared(&As_lo[r * PA + c]);
                LDSM_X4(ahi[mi][0], ahi[mi][1], ahi[mi][2], ahi[mi][3], ah);
                LDSM_X4(alo[mi][0], alo[mi][1], alo[mi][2], alo[mi][3], al);
            }
            #pragma unroll
            for (int nb = 0; nb < 2; nb++) {
                int r = kk + (lane & 15);
                int c = wn * 32 + nb * 16 + (lane >> 4) * 8;
                uint32_t bh = (uint32_t)__cvta_generic_to_shared(&Bs_hi[r * PB + c]);
                uint32_t bl = (uint32_t)__cvta_generic_to_shared(&Bs_lo[r * PB + c]);
                LDSM_X4_T(bhi[nb*2][0], bhi[nb*2][1], bhi[nb*2+1][0], bhi[nb*2+1][1], bh);
                LDSM_X4_T(blo[nb*2][0], blo[nb*2][1], blo[nb*2+1][0], blo[nb*2+1][1], bl);
            }

            #pragma unroll
            for (int mi = 0; mi < 4; mi++)
                #pragma unroll
                for (int ni = 0; ni < 4; ni++) {
                    MMA16816(acc[mi][ni], ahi[mi][0], ahi[mi][1], ahi[mi][2], ahi[mi][3],
                             bhi[ni][0], bhi[ni][1]);
                    MMA16816(acc[mi][ni], ahi[mi][0], ahi[mi][1], ahi[mi][2], ahi[mi][3],
                             blo[ni][0], blo[ni][1]);
                    MMA16816(acc[mi][ni], alo[mi][0], alo[mi][1], alo[mi][2], alo[mi][3],
                             bhi[ni][0], bhi[ni][1]);
                }
        }
        __syncthreads();
    }

    // epilogue
    int g = lane >> 2, t = lane & 3;
    #pragma unroll
    for (int mi = 0; mi < 4; mi++) {
        #pragma unroll
        for (int ni = 0; ni < 4; ni++) {
            int r = row0 + wm * 64 + mi * 16 + g;
            int c = col0 + wn * 32 + ni * 8 + t * 2;
            float v0 = acc[mi][ni][0], v1 = acc[mi][ni][1];
            float v2 = acc[mi][ni][2], v3 = acc[mi][ni][3];
            if (EPI >= 1) {
                float bz0 = bias[c], bz1 = bias[c + 1];
                v0 += bz0; v1 += bz1; v2 += bz0; v3 += bz1;
            }
            if (EPI == 1) {
                v0 = fmaxf(v0, 0.f); v1 = fmaxf(v1, 0.f);
                v2 = fmaxf(v2, 0.f); v3 = fmaxf(v3, 0.f);
            }
            float2* p0 = (float2*)&C[(size_t)r * N + c];
            float2* p1 = (float2*)&C[(size_t)(r + 8) * N + c];
            *p0 = make_float2(v0, v1);
            *p1 = make_float2(v2, v3);
        }
    }
}

// ---------------- flash attention (fp32 SIMT) -------------------------------
__global__ __launch_bounds__(256)
void attn_kernel(const float* __restrict__ Q,
                 const float* __restrict__ K,
                 const float* __restrict__ V,
                 const int*   __restrict__ vlen,
                 float* __restrict__ O)
{
    extern __shared__ float sm[];
    const int P = 65;
    float* Qs = sm;
    float* Ks = Qs + 64 * P;
    float* Vs = Ks + 64 * P;
    float* Ps = Vs + 64 * P;

    int tid = threadIdx.x;
    int bh  = blockIdx.y;
    int b   = bh >> 4;
    int h   = bh & 15;
    int q0  = blockIdx.x * 64;
    int vl  = vlen[b];

    const float* Qb = Q + (size_t)(b * SS) * DD + h * HD;
    const float* Kb = K + (size_t)(b * SS) * DD + h * HD;
    const float* Vb = V + (size_t)(b * SS) * DD + h * HD;

    #pragma unroll
    for (int it = 0; it < 4; it++) {
        int idx = tid + it * 256;
        int r = idx >> 4;
        int c = (idx & 15) * 4;
        float4 vq = *(const float4*)(Qb + (size_t)(q0 + r) * DD + c);
        Qs[r * P + c + 0] = vq.x;
        Qs[r * P + c + 1] = vq.y;
        Qs[r * P + c + 2] = vq.z;
        Qs[r * P + c + 3] = vq.w;
    }

    int tx = tid & 15, ty = tid >> 4;
    int qr = ty * 4;
    int dc = tx * 4;

    float m_i[4], l_i[4], o[4][4];
    #pragma unroll
    for (int i = 0; i < 4; i++) {
        m_i[i] = -1e30f;
        l_i[i] = 0.f;
        #pragma unroll
        for (int j = 0; j < 4; j++) o[i][j] = 0.f;
    }

    int nkt = (vl + 63) >> 6;
    for (int kt = 0; kt < nkt; kt++) {
        int k0 = kt * 64;
        __syncthreads();
        #pragma unroll
        for (int it = 0; it < 4; it++) {
            int idx = tid + it * 256;
            int r = idx >> 4;
            int c = (idx & 15) * 4;
            float4 vk = *(const float4*)(Kb + (size_t)(k0 + r) * DD + c);
            float4 vv = *(const float4*)(Vb + (size_t)(k0 + r) * DD + c);
            Ks[r * P + c + 0] = vk.x; Ks[r * P + c + 1] = vk.y;
            Ks[r * P + c + 2] = vk.z; Ks[r * P + c + 3] = vk.w;
            Vs[r * P + c + 0] = vv.x; Vs[r * P + c + 1] = vv.y;
            Vs[r * P + c + 2] = vv.z; Vs[r * P + c + 3] = vv.w;
        }
        __syncthreads();

        float s[4][4];
        #pragma unroll
        for (int i = 0; i < 4; i++)
            #pragma unroll
            for (int j = 0; j < 4; j++) s[i][j] = 0.f;
        #pragma unroll 8
        for (int d = 0; d < 64; d++) {
            float ar[4], br[4];
            #pragma unroll
            for (int i = 0; i < 4; i++) ar[i] = Qs[(qr + i) * P + d];
            #pragma unroll
            for (int j = 0; j < 4; j++) br[j] = Ks[(dc + j) * P + d];
            #pragma unroll
            for (int i = 0; i < 4; i++)
                #pragma unroll
                for (int j = 0; j < 4; j++)
                    s[i][j] += ar[i] * br[j];
        }
        #pragma unroll
        for (int i = 0; i < 4; i++)
            #pragma unroll
            for (int j = 0; j < 4; j++) {
                float v = s[i][j] * 0.125f;
                int kg = k0 + dc + j;
                s[i][j] = (kg < vl) ? v : -1e30f;
            }
        #pragma unroll
        for (int i = 0; i < 4; i++) {
            float rm = fmaxf(fmaxf(s[i][0], s[i][1]), fmaxf(s[i][2], s[i][3]));
            #pragma unroll
            for (int off = 8; off >= 1; off >>= 1)
                rm = fmaxf(rm, __shfl_xor_sync(0xffffffffu, rm, off));
            float mn = fmaxf(m_i[i], rm);
            float al = __expf(m_i[i] - mn);
            float rs = 0.f;
            #pragma unroll
            for (int j = 0; j < 4; j++) {
                float p = __expf(s[i][j] - mn);
                Ps[(qr + i) * P + dc + j] = p;
                rs += p;
            }
            #pragma unroll
            for (int off = 8; off >= 1; off >>= 1)
                rs += __shfl_xor_sync(0xffffffffu, rs, off);
            l_i[i] = l_i[i] * al + rs;
            m_i[i] = mn;
            #pragma unroll
            for (int j = 0; j < 4; j++) o[i][j] *= al;
        }
        __syncthreads();

        #pragma unroll 8
        for (int k = 0; k < 64; k++) {
            float pa2[4], vb2[4];
            #pragma unroll
            for (int i = 0; i < 4; i++) pa2[i] = Ps[(qr + i) * P + k];
            #pragma unroll
            for (int j = 0; j < 4; j++) vb2[j] = Vs[k * P + dc + j];
            #pragma unroll
            for (int i = 0; i < 4; i++)
                #pragma unroll
                for (int j = 0; j < 4; j++)
                    o[i][j] += pa2[i] * vb2[j];
        }
    }

    float* Ob = O + (size_t)(b * SS) * DD + h * HD;
    #pragma unroll
    for (int i = 0; i < 4; i++) {
        float inv = 1.f / l_i[i];
        #pragma unroll
        for (int j = 0; j < 4; j++)
            Ob[(size_t)(q0 + qr + i) * DD + dc + j] = o[i][j] * inv;
    }
}

// ---------------- fused residual + LayerNorm -------------------------------
__global__ __launch_bounds__(256)
void ln_kernel(const float* __restrict__ A,
               const float* __restrict__ R,
               const float* __restrict__ g,
               const float* __restrict__ be,
               float* __restrict__ out)
{
    int row = blockIdx.x;
    int t   = threadIdx.x;
    const float4* a4 = (const float4*)(A + (size_t)row * DD);
    const float4* r4 = (const float4*)(R + (size_t)row * DD);
    float4 av = a4[t];
    float4 rv = r4[t];
    float x0 = av.x + rv.x, x1 = av.y + rv.y, x2 = av.z + rv.z, x3 = av.w + rv.w;

    float s = x0 + x1 + x2 + x3;
    float q = x0 * x0 + x1 * x1 + x2 * x2 + x3 * x3;
    #pragma unroll
    for (int off = 16; off >= 1; off >>= 1) {
        s += __shfl_xor_sync(0xffffffffu, s, off);
        q += __shfl_xor_sync(0xffffffffu, q, off);
    }
    __shared__ float rs[8], rq[8];
    int w = t >> 5, lane = t & 31;
    if (lane == 0) { rs[w] = s; rq[w] = q; }
    __syncthreads();
    float tot = 0.f, totq = 0.f;
    #pragma unroll
    for (int i = 0; i < 8; i++) { tot += rs[i]; totq += rq[i]; }

    float mean = tot * (1.f / DD);
    float var  = totq * (1.f / DD) - mean * mean;
    float rstd = rsqrtf(var + EPSL);

    float4 gv = ((const float4*)g)[t];
    float4 bv = ((const float4*)be)[t];
    float4 ov;
    ov.x = (x0 - mean) * rstd * gv.x + bv.x;
    ov.y = (x1 - mean) * rstd * gv.y + bv.y;
    ov.z = (x2 - mean) * rstd * gv.z + bv.z;
    ov.w = (x3 - mean) * rstd * gv.w + bv.w;
    ((float4*)(out + (size_t)row * DD))[t] = ov;
}

// ---------------- launch ----------------------------------------------------
extern "C" void kernel_launch(void* const* d_in, const int* in_sizes, int n_in,
                              void* d_out, int out_size)
{
    const float* x   = (const float*)d_in[0];
    const int*   vl  = (const int*)  d_in[1];
    const float* Wq  = (const float*)d_in[2];
    const float* Wk  = (const float*)d_in[3];
    const float* Wv  = (const float*)d_in[4];
    const float* Wo  = (const float*)d_in[5];
    const float* W1  = (const float*)d_in[6];
    const float* b1  = (const float*)d_in[7];
    const float* W2  = (const float*)d_in[8];
    const float* b2  = (const float*)d_in[9];
    const float* g1  = (const float*)d_in[10];
    const float* be1 = (const float*)d_in[11];
    const float* g2  = (const float*)d_in[12];
    const float* be2 = (const float*)d_in[13];
    float* out = (float*)d_out;

    float *q, *k, *v, *a, *r, *ff;
    cudaGetSymbolAddress((void**)&q,  g_q);
    cudaGetSymbolAddress((void**)&k,  g_k);
    cudaGetSymbolAddress((void**)&v,  g_v);
    cudaGetSymbolAddress((void**)&a,  g_a);
    cudaGetSymbolAddress((void**)&r,  g_r);
    cudaGetSymbolAddress((void**)&ff, g_ff);

    int attn_smem = 4 * 64 * 65 * (int)sizeof(float);
    cudaFuncSetAttribute(attn_kernel,
                         cudaFuncAttributeMaxDynamicSharedMemorySize, attn_smem);

    dim3 gD(DD / 128, NR / 128);     // (8, 64)
    dim3 gF(FF / 128, NR / 128);     // (32, 64)

    // QKV projections (tensor cores)
    hgemm_kernel<0><<<gD, 256>>>(NR, DD, DD, x, Wq, nullptr, q);
    hgemm_kernel<0><<<gD, 256>>>(NR, DD, DD, x, Wk, nullptr, k);
    hgemm_kernel<0><<<gD, 256>>>(NR, DD, DD, x, Wv, nullptr, v);

    // attention
    attn_kernel<<<dim3(SS / 64, BB * HH), 256, attn_smem>>>(q, k, v, vl, a);

    // output projection
    hgemm_kernel<0><<<gD, 256>>>(NR, DD, DD, a, Wo, nullptr, q);

    // residual + LN1 -> r
    ln_kernel<<<NR, 256>>>(q, x, g1, be1, r);

    // FFN
    hgemm_kernel<1><<<gF, 256>>>(NR, FF, DD, r, W1, b1, ff);   // +b1, relu
    hgemm_kernel<2><<<gD, 256>>>(NR, DD, FF, ff, W2, b2, k);   // +b2

    // residual + LN2 -> output
    ln_kernel<<<NR, 256>>>(k, r, g2, be2, out);
}

// round 4
// speedup vs baseline: 2.4754x; 1.3022x over previous
#include <cuda_runtime.h>
#include <cuda_bf16.h>
#include <math.h>
#include <stdint.h>

// Problem constants
#define BB   4
#define SS   2048
#define DD   1024
#define HH   16
#define HD   64
#define FF   4096
#define NR   (BB*SS)          // 8192 rows
#define EPSL 1e-5f

// ---------------- scratch (device globals; no allocation allowed) ----------
__device__ float g_q [NR*DD];
__device__ float g_k [NR*DD];
__device__ float g_v [NR*DD];
__device__ float g_a [NR*DD];
__device__ float g_r [NR*DD];
__device__ float g_ff[(size_t)NR*FF];

// ---------------- mma helpers ----------------------------------------------
#define LDSM_X4(R0,R1,R2,R3,ADDR) \
    asm volatile("ldmatrix.sync.aligned.m8n8.x4.shared.b16 {%0,%1,%2,%3},[%4];" \
        : "=r"(R0),"=r"(R1),"=r"(R2),"=r"(R3) : "r"(ADDR))

#define LDSM_X4_T(R0,R1,R2,R3,ADDR) \
    asm volatile("ldmatrix.sync.aligned.m8n8.x4.trans.shared.b16 {%0,%1,%2,%3},[%4];" \
        : "=r"(R0),"=r"(R1),"=r"(R2),"=r"(R3) : "r"(ADDR))

#define MMA16816(D,A0,A1,A2,A3,B0,B1) \
    asm volatile("mma.sync.aligned.m16n8k16.row.col.f32.bf16.bf16.f32 " \
        "{%0,%1,%2,%3},{%4,%5,%6,%7},{%8,%9},{%0,%1,%2,%3};" \
        : "+f"(D[0]),"+f"(D[1]),"+f"(D[2]),"+f"(D[3]) \
        : "r"(A0),"r"(A1),"r"(A2),"r"(A3),"r"(B0),"r"(B1))

__device__ __forceinline__ uint32_t pack_bf2(float a, float b) {
    __nv_bfloat162 h = __floats2bfloat162_rn(a, b);   // x=a (low), y=b (high)
    return *reinterpret_cast<uint32_t*>(&h);
}

// fast exp on the FMA pipe (no MUFU). x <= 0 expected. ~2e-6 rel err.
__device__ __forceinline__ float expf_fast(float x) {
    float y = fmaxf(x * 1.44269504088896f, -126.f);
    float fl = floorf(y);
    float f = y - fl;
    float p = 1.54653240e-4f;
    p = fmaf(p, f, 1.33335581e-3f);
    p = fmaf(p, f, 9.61812910e-3f);
    p = fmaf(p, f, 5.55041086e-2f);
    p = fmaf(p, f, 2.40226507e-1f);
    p = fmaf(p, f, 6.93147181e-1f);
    p = fmaf(p, f, 1.0f);
    int ei = (int)fl;
    float sc = __int_as_float((ei + 127) << 23);
    return p * sc;
}

// ---------------- tensor-core GEMM (3xBF16 split) ---------------------------
template<int EPI>   // 0 plain, 1 +bias+relu, 2 +bias
__global__ __launch_bounds__(256, 1)
void hgemm_kernel(int M, int N, int K,
                  const float* __restrict__ A,
                  const float* __restrict__ B,
                  const float* __restrict__ bias,
                  float* __restrict__ C)
{
    const int BK = 32;
    const int PA = 40;
    const int PB = 136;

    __shared__ __align__(16) __nv_bfloat16 As_hi[128 * PA];
    __shared__ __align__(16) __nv_bfloat16 As_lo[128 * PA];
    __shared__ __align__(16) __nv_bfloat16 Bs_hi[32 * PB];
    __shared__ __align__(16) __nv_bfloat16 Bs_lo[32 * PB];

    int tid  = threadIdx.x;
    int lane = tid & 31;
    int warp = tid >> 5;
    int wm = warp & 1;
    int wn = warp >> 1;
    int row0 = blockIdx.y * 128;
    int col0 = blockIdx.x * 128;

    float acc[4][4][4];
    #pragma unroll
    for (int i = 0; i < 4; i++)
        #pragma unroll
        for (int j = 0; j < 4; j++)
            #pragma unroll
            for (int c = 0; c < 4; c++) acc[i][j][c] = 0.f;

    float4 pa[4], pb[4];
    #pragma unroll
    for (int it = 0; it < 4; it++) {
        int idx = it * 256 + tid;
        pa[it] = *(const float4*)(A + (size_t)(row0 + (idx >> 3)) * K + (idx & 7) * 4);
        pb[it] = *(const float4*)(B + (size_t)(idx >> 5) * N + col0 + (idx & 31) * 4);
    }

    for (int kt = 0; kt < K; kt += BK) {
        #pragma unroll
        for (int it = 0; it < 4; it++) {
            int idx = it * 256 + tid;
            {
                int r = idx >> 3, c = (idx & 7) * 4;
                float vv[4] = {pa[it].x, pa[it].y, pa[it].z, pa[it].w};
                #pragma unroll
                for (int j = 0; j < 4; j++) {
                    __nv_bfloat16 h = __float2bfloat16(vv[j]);
                    As_hi[r * PA + c + j] = h;
                    As_lo[r * PA + c + j] = __float2bfloat16(vv[j] - __bfloat162float(h));
                }
            }
            {
                int r = idx >> 5, c = (idx & 31) * 4;
                float vv[4] = {pb[it].x, pb[it].y, pb[it].z, pb[it].w};
                #pragma unroll
                for (int j = 0; j < 4; j++) {
                    __nv_bfloat16 h = __float2bfloat16(vv[j]);
                    Bs_hi[r * PB + c + j] = h;
                    Bs_lo[r * PB + c + j] = __float2bfloat16(vv[j] - __bfloat162float(h));
                }
            }
        }
        __syncthreads();

        if (kt + BK < K) {
            #pragma unroll
            for (int it = 0; it < 4; it++) {
                int idx = it * 256 + tid;
                pa[it] = *(const float4*)(A + (size_t)(row0 + (idx >> 3)) * K + kt + BK + (idx & 7) * 4);
                pb[it] = *(const float4*)(B + (size_t)(kt + BK + (idx >> 5)) * N + col0 + (idx & 31) * 4);
            }
        }

        #pragma unroll
        for (int kk = 0; kk < BK; kk += 16) {
            uint32_t ahi[4][4], alo[4][4], bhi[4][2], blo[4][2];

            #pragma unroll
            for (int mi = 0; mi < 4; mi++) {
                int r = wm * 64 + mi * 16 + (lane & 15);
                int c = kk + (lane >> 4) * 8;
                uint32_t ah = (uint32_t)__cvta_generic_to_shared(&As_hi[r * PA + c]);
                uint32_t al = (uint32_t)__cvta_generic_to_shared(&As_lo[r * PA + c]);
                LDSM_X4(ahi[mi][0], ahi[mi][1], ahi[mi][2], ahi[mi][3], ah);
                LDSM_X4(alo[mi][0], alo[mi][1], alo[mi][2], alo[mi][3], al);
            }
            #pragma unroll
            for (int nb = 0; nb < 2; nb++) {
                int r = kk + (lane & 15);
                int c = wn * 32 + nb * 16 + (lane >> 4) * 8;
                uint32_t bh = (uint32_t)__cvta_generic_to_shared(&Bs_hi[r * PB + c]);
                uint32_t bl = (uint32_t)__cvta_generic_to_shared(&Bs_lo[r * PB + c]);
                LDSM_X4_T(bhi[nb*2][0], bhi[nb*2][1], bhi[nb*2+1][0], bhi[nb*2+1][1], bh);
                LDSM_X4_T(blo[nb*2][0], blo[nb*2][1], blo[nb*2+1][0], blo[nb*2+1][1], bl);
            }

            #pragma unroll
            for (int mi = 0; mi < 4; mi++)
                #pragma unroll
                for (int ni = 0; ni < 4; ni++) {
                    MMA16816(acc[mi][ni], ahi[mi][0], ahi[mi][1], ahi[mi][2], ahi[mi][3],
                             bhi[ni][0], bhi[ni][1]);
                    MMA16816(acc[mi][ni], ahi[mi][0], ahi[mi][1], ahi[mi][2], ahi[mi][3],
                             blo[ni][0], blo[ni][1]);
                    MMA16816(acc[mi][ni], alo[mi][0], alo[mi][1], alo[mi][2], alo[mi][3],
                             bhi[ni][0], bhi[ni][1]);
                }
        }
        __syncthreads();
    }

    int g = lane >> 2, t = lane & 3;
    #pragma unroll
    for (int mi = 0; mi < 4; mi++) {
        #pragma unroll
        for (int ni = 0; ni < 4; ni++) {
            int r = row0 + wm * 64 + mi * 16 + g;
            int c = col0 + wn * 32 + ni * 8 + t * 2;
            float v0 = acc[mi][ni][0], v1 = acc[mi][ni][1];
            float v2 = acc[mi][ni][2], v3 = acc[mi][ni][3];
            if (EPI >= 1) {
                float bz0 = bias[c], bz1 = bias[c + 1];
                v0 += bz0; v1 += bz1; v2 += bz0; v3 += bz1;
            }
            if (EPI == 1) {
                v0 = fmaxf(v0, 0.f); v1 = fmaxf(v1, 0.f);
                v2 = fmaxf(v2, 0.f); v3 = fmaxf(v3, 0.f);
            }
            float2* p0 = (float2*)&C[(size_t)r * N + c];
            float2* p1 = (float2*)&C[(size_t)(r + 8) * N + c];
            *p0 = make_float2(v0, v1);
            *p1 = make_float2(v2, v3);
        }
    }
}

// ---------------- tensor-core flash attention --------------------------------
// grid (S/64, B*H), 128 threads (4 warps). Each warp: 16 q-rows x full head.
// 64-key tiles, online softmax, split-bf16 (3-term) for QK^T and PV.
// Key loop stops at ceil(vl/64) (exp underflow makes masked keys exactly 0).
#define APAD 72   // smem pitch in halves (144B rows; conflict-free for ldmatrix)

__global__ __launch_bounds__(128)
void attn_mma_kernel(const float* __restrict__ Q,
                     const float* __restrict__ K,
                     const float* __restrict__ V,
                     const int*   __restrict__ vlen,
                     float* __restrict__ O)
{
    __shared__ __align__(16) __nv_bfloat16 Ks_hi[64 * APAD];
    __shared__ __align__(16) __nv_bfloat16 Ks_lo[64 * APAD];
    __shared__ __align__(16) __nv_bfloat16 Vs_hi[64 * APAD];
    __shared__ __align__(16) __nv_bfloat16 Vs_lo[64 * APAD];

    int tid  = threadIdx.x;
    int lane = tid & 31;
    int warp = tid >> 5;
    int g    = lane >> 2;
    int t    = lane & 3;

    int bh = blockIdx.y;
    int b  = bh >> 4;
    int h  = bh & 15;
    int q0 = blockIdx.x * 64;
    int vl = vlen[b];

    const float* Qb = Q + (size_t)(b * SS) * DD + h * HD;
    const float* Kb = K + (size_t)(b * SS) * DD + h * HD;
    const float* Vb = V + (size_t)(b * SS) * DD + h * HD;

    // ---- stage Q tile (64x64) into Ks_hi/lo, pull fragments, then reuse smem
    #pragma unroll
    for (int it = 0; it < 8; it++) {
        int idx = it * 128 + tid;
        int r = idx >> 4, c = (idx & 15) * 4;
        float4 v = *(const float4*)(Qb + (size_t)(q0 + r) * DD + c);
        float vv[4] = {v.x, v.y, v.z, v.w};
        #pragma unroll
        for (int j = 0; j < 4; j++) {
            __nv_bfloat16 hi = __float2bfloat16(vv[j]);
            Ks_hi[r * APAD + c + j] = hi;
            Ks_lo[r * APAD + c + j] = __float2bfloat16(vv[j] - __bfloat162float(hi));
        }
    }
    __syncthreads();

    uint32_t qh[4][4], ql[4][4];
    #pragma unroll
    for (int kk = 0; kk < 4; kk++) {
        int r = warp * 16 + (lane & 15);
        int c = kk * 16 + (lane >> 4) * 8;
        uint32_t ah = (uint32_t)__cvta_generic_to_shared(&Ks_hi[r * APAD + c]);
        uint32_t al = (uint32_t)__cvta_generic_to_shared(&Ks_lo[r * APAD + c]);
        LDSM_X4(qh[kk][0], qh[kk][1], qh[kk][2], qh[kk][3], ah);
        LDSM_X4(ql[kk][0], ql[kk][1], ql[kk][2], ql[kk][3], al);
    }

    float o[8][4];
    #pragma unroll
    for (int i = 0; i < 8; i++)
        #pragma unroll
        for (int c = 0; c < 4; c++) o[i][c] = 0.f;
    float m0 = -1e30f, m1 = -1e30f, l0 = 0.f, l1 = 0.f;

    int nkt = (vl + 63) >> 6;
    for (int kt = 0; kt < nkt; kt++) {
        int k0 = kt * 64;
        __syncthreads();   // fragment reads of prev tile done before overwrite

        // load + split K,V tiles
        #pragma unroll
        for (int it = 0; it < 8; it++) {
            int idx = it * 128 + tid;
            int r = idx >> 4, c = (idx & 15) * 4;
            float4 kv = *(const float4*)(Kb + (size_t)(k0 + r) * DD + c);
            float4 vv = *(const float4*)(Vb + (size_t)(k0 + r) * DD + c);
            float ka[4] = {kv.x, kv.y, kv.z, kv.w};
            float va[4] = {vv.x, vv.y, vv.z, vv.w};
            #pragma unroll
            for (int j = 0; j < 4; j++) {
                __nv_bfloat16 hi = __float2bfloat16(ka[j]);
                Ks_hi[r * APAD + c + j] = hi;
                Ks_lo[r * APAD + c + j] = __float2bfloat16(ka[j] - __bfloat162float(hi));
                __nv_bfloat16 vh = __float2bfloat16(va[j]);
                Vs_hi[r * APAD + c + j] = vh;
                Vs_lo[r * APAD + c + j] = __float2bfloat16(va[j] - __bfloat162float(vh));
            }
        }
        __syncthreads();

        // ---- S = Q K^T  (8 n8-blocks of keys x 4 accum floats)
        float s[8][4];
        #pragma unroll
        for (int i = 0; i < 8; i++)
            #pragma unroll
            for (int c = 0; c < 4; c++) s[i][c] = 0.f;

        #pragma unroll
        for (int kk = 0; kk < 4; kk++) {
            #pragma unroll
            for (int nb = 0; nb < 4; nb++) {
                int r = nb * 16 + (lane & 15);
                int c = kk * 16 + (lane >> 4) * 8;
                uint32_t kha = (uint32_t)__cvta_generic_to_shared(&Ks_hi[r * APAD + c]);
                uint32_t kla = (uint32_t)__cvta_generic_to_shared(&Ks_lo[r * APAD + c]);
                uint32_t kh0, kh1, kh2, kh3, kl0, kl1, kl2, kl3;
                LDSM_X4(kh0, kh1, kh2, kh3, kha);
                LDSM_X4(kl0, kl1, kl2, kl3, kla);
                // n8 block 2nb: keys nb*16..+7  -> pairs (r0, r2)
                MMA16816(s[2*nb],   qh[kk][0], qh[kk][1], qh[kk][2], qh[kk][3], kh0, kh2);
                MMA16816(s[2*nb],   qh[kk][0], qh[kk][1], qh[kk][2], qh[kk][3], kl0, kl2);
                MMA16816(s[2*nb],   ql[kk][0], ql[kk][1], ql[kk][2], ql[kk][3], kh0, kh2);
                // n8 block 2nb+1: keys nb*16+8..+15 -> pairs (r1, r3)
                MMA16816(s[2*nb+1], qh[kk][0], qh[kk][1], qh[kk][2], qh[kk][3], kh1, kh3);
                MMA16816(s[2*nb+1], qh[kk][0], qh[kk][1], qh[kk][2], qh[kk][3], kl1, kl3);
                MMA16816(s[2*nb+1], ql[kk][0], ql[kk][1], ql[kk][2], ql[kk][3], kh1, kh3);
            }
        }

        // ---- scale + mask
        #pragma unroll
        for (int nb = 0; nb < 8; nb++) {
            int c0 = k0 + nb * 8 + 2 * t;
            int c1 = c0 + 1;
            s[nb][0] = (c0 < vl) ? s[nb][0] * 0.125f : -1e30f;
            s[nb][1] = (c1 < vl) ? s[nb][1] * 0.125f : -1e30f;
            s[nb][2] = (c0 < vl) ? s[nb][2] * 0.125f : -1e30f;
            s[nb][3] = (c1 < vl) ? s[nb][3] * 0.125f : -1e30f;
        }

        // ---- row max (rows g and g+8), reduce over quad lanes
        float tm0 = -1e30f, tm1 = -1e30f;
        #pragma unroll
        for (int nb = 0; nb < 8; nb++) {
            tm0 = fmaxf(tm0, fmaxf(s[nb][0], s[nb][1]));
            tm1 = fmaxf(tm1, fmaxf(s[nb][2], s[nb][3]));
        }
        tm0 = fmaxf(tm0, __shfl_xor_sync(0xffffffffu, tm0, 1));
        tm0 = fmaxf(tm0, __shfl_xor_sync(0xffffffffu, tm0, 2));
        tm1 = fmaxf(tm1, __shfl_xor_sync(0xffffffffu, tm1, 1));
        tm1 = fmaxf(tm1, __shfl_xor_sync(0xffffffffu, tm1, 2));

        float mn0 = fmaxf(m0, tm0);
        float mn1 = fmaxf(m1, tm1);
        float al0 = expf_fast(m0 - mn0);
        float al1 = expf_fast(m1 - mn1);

        // ---- p = exp(s - m), pack into A-fragments (hi/lo), accumulate row sums
        uint32_t pAh[4][4], pAl[4][4];
        float ls0 = 0.f, ls1 = 0.f;
        #pragma unroll
        for (int nb = 0; nb < 8; nb++) {
            float p0 = expf_fast(s[nb][0] - mn0);
            float p1 = expf_fast(s[nb][1] - mn0);
            float p2 = expf_fast(s[nb][2] - mn1);
            float p3 = expf_fast(s[nb][3] - mn1);
            ls0 += p0 + p1;
            ls1 += p2 + p3;
            float h0 = __bfloat162float(__float2bfloat16(p0));
            float h1 = __bfloat162float(__float2bfloat16(p1));
            float h2 = __bfloat162float(__float2bfloat16(p2));
            float h3 = __bfloat162float(__float2bfloat16(p3));
            int ks = nb >> 1;
            int hf = (nb & 1) * 2;
            pAh[ks][hf + 0] = pack_bf2(h0, h1);
            pAh[ks][hf + 1] = pack_bf2(h2, h3);
            pAl[ks][hf + 0] = pack_bf2(p0 - h0, p1 - h1);
            pAl[ks][hf + 1] = pack_bf2(p2 - h2, p3 - h3);
        }
        ls0 += __shfl_xor_sync(0xffffffffu, ls0, 1);
        ls0 += __shfl_xor_sync(0xffffffffu, ls0, 2);
        ls1 += __shfl_xor_sync(0xffffffffu, ls1, 1);
        ls1 += __shfl_xor_sync(0xffffffffu, ls1, 2);

        l0 = l0 * al0 + ls0;
        l1 = l1 * al1 + ls1;
        m0 = mn0;
        m1 = mn1;

        #pragma unroll
        for (int nb = 0; nb < 8; nb++) {
            o[nb][0] *= al0; o[nb][1] *= al0;
            o[nb][2] *= al1; o[nb][3] *= al1;
        }

        // ---- O += P V
        #pragma unroll
        for (int kk = 0; kk < 4; kk++) {      // keys 16kk..
            // fix a-frag ordering: a0=(g,k lo), a1=(g+8,k lo), a2=(g,k hi), a3=(g+8,k hi)
            uint32_t a0h = pAh[kk][0], a1h = pAh[kk][1], a2h = pAh[kk][2], a3h = pAh[kk][3];
            uint32_t a0l = pAl[kk][0], a1l = pAl[kk][1], a2l = pAl[kk][2], a3l = pAl[kk][3];
            #pragma unroll
            for (int nb = 0; nb < 4; nb++) {  // dims 16nb..
                int r = kk * 16 + (lane & 15);
                int c = nb * 16 + (lane >> 4) * 8;
                uint32_t vha = (uint32_t)__cvta_generic_to_shared(&Vs_hi[r * APAD + c]);
                uint32_t vla = (uint32_t)__cvta_generic_to_shared(&Vs_lo[r * APAD + c]);
                uint32_t vh0, vh1, vh2, vh3, vl0_, vl1_, vl2_, vl3_;
                LDSM_X4_T(vh0, vh1, vh2, vh3, vha);
                LDSM_X4_T(vl0_, vl1_, vl2_, vl3_, vla);
                // dims-lo n8 block: pairs (r0, r1); dims-hi: (r2, r3)
                MMA16816(o[2*nb],   a0h, a1h, a2h, a3h, vh0, vh1);
                MMA16816(o[2*nb],   a0h, a1h, a2h, a3h, vl0_, vl1_);
                MMA16816(o[2*nb],   a0l, a1l, a2l, a3l, vh0, vh1);
                MMA16816(o[2*nb+1], a0h, a1h, a2h, a3h, vh2, vh3);
                MMA16816(o[2*nb+1], a0h, a1h, a2h, a3h, vl2_, vl3_);
                MMA16816(o[2*nb+1], a0l, a1l, a2l, a3l, vh2, vh3);
            }
        }
    }

    // ---- epilogue: normalize and store
    float inv0 = 1.f / l0;
    float inv1 = 1.f / l1;
    int row0g = q0 + warp * 16 + g;
    int row1g = row0g + 8;
    float* Ob = O + (size_t)(b * SS) * DD + h * HD;
    #pragma unroll
    for (int nb = 0; nb < 8; nb++) {
        int col = nb * 8 + 2 * t;
        *(float2*)(Ob + (size_t)row0g * DD + col) = make_float2(o[nb][0] * inv0, o[nb][1] * inv0);
        *(float2*)(Ob + (size_t)row1g * DD + col) = make_float2(o[nb][2] * inv1, o[nb][3] * inv1);
    }
}

// ---------------- fused residual + LayerNorm -------------------------------
__global__ __launch_bounds__(256)
void ln_kernel(const float* __restrict__ A,
               const float* __restrict__ R,
               const float* __restrict__ g,
               const float* __restrict__ be,
               float* __restrict__ out)
{
    int row = blockIdx.x;
    int t   = threadIdx.x;
    const float4* a4 = (const float4*)(A + (size_t)row * DD);
    const float4* r4 = (const float4*)(R + (size_t)row * DD);
    float4 av = a4[t];
    float4 rv = r4[t];
    float x0 = av.x + rv.x, x1 = av.y + rv.y, x2 = av.z + rv.z, x3 = av.w + rv.w;

    float s = x0 + x1 + x2 + x3;
    float q = x0 * x0 + x1 * x1 + x2 * x2 + x3 * x3;
    #pragma unroll
    for (int off = 16; off >= 1; off >>= 1) {
        s += __shfl_xor_sync(0xffffffffu, s, off);
        q += __shfl_xor_sync(0xffffffffu, q, off);
    }
    __shared__ float rs[8], rq[8];
    int w = t >> 5, lane = t & 31;
    if (lane == 0) { rs[w] = s; rq[w] = q; }
    __syncthreads();
    float tot = 0.f, totq = 0.f;
    #pragma unroll
    for (int i = 0; i < 8; i++) { tot += rs[i]; totq += rq[i]; }

    float mean = tot * (1.f / DD);
    float var  = totq * (1.f / DD) - mean * mean;
    float rstd = rsqrtf(var + EPSL);

    float4 gv = ((const float4*)g)[t];
    float4 bv = ((const float4*)be)[t];
    float4 ov;
    ov.x = (x0 - mean) * rstd * gv.x + bv.x;
    ov.y = (x1 - mean) * rstd * gv.y + bv.y;
    ov.z = (x2 - mean) * rstd * gv.z + bv.z;
    ov.w = (x3 - mean) * rstd * gv.w + bv.w;
    ((float4*)(out + (size_t)row * DD))[t] = ov;
}

// ---------------- launch ----------------------------------------------------
extern "C" void kernel_launch(void* const* d_in, const int* in_sizes, int n_in,
                              void* d_out, int out_size)
{
    const float* x   = (const float*)d_in[0];
    const int*   vl  = (const int*)  d_in[1];
    const float* Wq  = (const float*)d_in[2];
    const float* Wk  = (const float*)d_in[3];
    const float* Wv  = (const float*)d_in[4];
    const float* Wo  = (const float*)d_in[5];
    const float* W1  = (const float*)d_in[6];
    const float* b1  = (const float*)d_in[7];
    const float* W2  = (const float*)d_in[8];
    const float* b2  = (const float*)d_in[9];
    const float* g1  = (const float*)d_in[10];
    const float* be1 = (const float*)d_in[11];
    const float* g2  = (const float*)d_in[12];
    const float* be2 = (const float*)d_in[13];
    float* out = (float*)d_out;

    float *q, *k, *v, *a, *r, *ff;
    cudaGetSymbolAddress((void**)&q,  g_q);
    cudaGetSymbolAddress((void**)&k,  g_k);
    cudaGetSymbolAddress((void**)&v,  g_v);
    cudaGetSymbolAddress((void**)&a,  g_a);
    cudaGetSymbolAddress((void**)&r,  g_r);
    cudaGetSymbolAddress((void**)&ff, g_ff);

    dim3 gD(DD / 128, NR / 128);     // (8, 64)
    dim3 gF(FF / 128, NR / 128);     // (32, 64)

    // QKV projections (tensor cores)
    hgemm_kernel<0><<<gD, 256>>>(NR, DD, DD, x, Wq, nullptr, q);
    hgemm_kernel<0><<<gD, 256>>>(NR, DD, DD, x, Wk, nullptr, k);
    hgemm_kernel<0><<<gD, 256>>>(NR, DD, DD, x, Wv, nullptr, v);

    // attention (tensor cores)
    attn_mma_kernel<<<dim3(SS / 64, BB * HH), 128>>>(q, k, v, vl, a);

    // output projection
    hgemm_kernel<0><<<gD, 256>>>(NR, DD, DD, a, Wo, nullptr, q);

    // residual + LN1 -> r
    ln_kernel<<<NR, 256>>>(q, x, g1, be1, r);

    // FFN
    hgemm_kernel<1><<<gF, 256>>>(NR, FF, DD, r, W1, b1, ff);   // +b1, relu
    hgemm_kernel<2><<<gD, 256>>>(NR, DD, FF, ff, W2, b2, k);   // +b2

    // residual + LN2 -> output
    ln_kernel<<<NR, 256>>>(k, r, g2, be2, out);
}

// round 6
// speedup vs baseline: 2.5410x; 1.0265x over previous
#include <cuda_runtime.h>
#include <cuda_bf16.h>
#include <math.h>
#include <stdint.h>

// Problem constants
#define BB   4
#define SS   2048
#define DD   1024
#define HH   16
#define HD   64
#define FF   4096
#define NR   (BB*SS)          // 8192 rows
#define EPSL 1e-5f

// ---------------- scratch (device globals; no allocation allowed) ----------
__device__ float g_q [NR*DD];
__device__ float g_k [NR*DD];
__device__ float g_v [NR*DD];
__device__ float g_r [NR*DD];

// bf16 hi/lo splits of activations
__device__ __align__(16) __nv_bfloat16 g_xh[NR*DD],  g_xl[NR*DD];
__device__ __align__(16) __nv_bfloat16 g_ah[NR*DD],  g_al[NR*DD];
__device__ __align__(16) __nv_bfloat16 g_rh[NR*DD],  g_rl[NR*DD];
__device__ __align__(16) __nv_bfloat16 g_ffh[(size_t)NR*FF], g_ffl[(size_t)NR*FF];

// bf16 hi/lo splits of weights (same [K,N] layout as input)
__device__ __align__(16) __nv_bfloat16 g_wqh[DD*DD], g_wql[DD*DD];
__device__ __align__(16) __nv_bfloat16 g_wkh[DD*DD], g_wkl[DD*DD];
__device__ __align__(16) __nv_bfloat16 g_wvh[DD*DD], g_wvl[DD*DD];
__device__ __align__(16) __nv_bfloat16 g_woh[DD*DD], g_wol[DD*DD];
__device__ __align__(16) __nv_bfloat16 g_w1h[(size_t)DD*FF], g_w1l[(size_t)DD*FF];
__device__ __align__(16) __nv_bfloat16 g_w2h[(size_t)DD*FF], g_w2l[(size_t)DD*FF];

// ---------------- mma / cp.async helpers ------------------------------------
#define LDSM_X4(R0,R1,R2,R3,ADDR) \
    asm volatile("ldmatrix.sync.aligned.m8n8.x4.shared.b16 {%0,%1,%2,%3},[%4];" \
        : "=r"(R0),"=r"(R1),"=r"(R2),"=r"(R3) : "r"(ADDR))

#define LDSM_X4_T(R0,R1,R2,R3,ADDR) \
    asm volatile("ldmatrix.sync.aligned.m8n8.x4.trans.shared.b16 {%0,%1,%2,%3},[%4];" \
        : "=r"(R0),"=r"(R1),"=r"(R2),"=r"(R3) : "r"(ADDR))

#define MMA16816(D,A0,A1,A2,A3,B0,B1) \
    asm volatile("mma.sync.aligned.m16n8k16.row.col.f32.bf16.bf16.f32 " \
        "{%0,%1,%2,%3},{%4,%5,%6,%7},{%8,%9},{%0,%1,%2,%3};" \
        : "+f"(D[0]),"+f"(D[1]),"+f"(D[2]),"+f"(D[3]) \
        : "r"(A0),"r"(A1),"r"(A2),"r"(A3),"r"(B0),"r"(B1))

__device__ __forceinline__ void cp16(uint32_t dst, const void* src) {
    asm volatile("cp.async.cg.shared.global [%0],[%1],16;" :: "r"(dst), "l"(src));
}
#define CP_COMMIT() asm volatile("cp.async.commit_group;" ::: "memory")
#define CP_WAIT1()  asm volatile("cp.async.wait_group 1;" ::: "memory")

__device__ __forceinline__ uint32_t pack_bf2(float a, float b) {
    __nv_bfloat162 h = __floats2bfloat162_rn(a, b);
    return *reinterpret_cast<uint32_t*>(&h);
}

// fast exp on the FMA pipe (no MUFU). x <= 0 expected. ~2e-6 rel err.
__device__ __forceinline__ float expf_fast(float x) {
    float y = fmaxf(x * 1.44269504088896f, -126.f);
    float fl = floorf(y);
    float f = y - fl;
    float p = 1.54653240e-4f;
    p = fmaf(p, f, 1.33335581e-3f);
    p = fmaf(p, f, 9.61812910e-3f);
    p = fmaf(p, f, 5.55041086e-2f);
    p = fmaf(p, f, 2.40226507e-1f);
    p = fmaf(p, f, 6.93147181e-1f);
    p = fmaf(p, f, 1.0f);
    int ei = (int)fl;
    float sc = __int_as_float((ei + 127) << 23);
    return p * sc;
}

// ---------------- elementwise fp32 -> bf16 hi/lo split ----------------------
// n4 = total elements / 4. grid*256 == n4.
__global__ __launch_bounds__(256)
void wsplit_kernel(const float* __restrict__ W,
                   __nv_bfloat16* __restrict__ H,
                   __nv_bfloat16* __restrict__ L)
{
    size_t i = (size_t)blockIdx.x * 256 + threadIdx.x;
    float4 v = ((const float4*)W)[i];
    float a[4] = {v.x, v.y, v.z, v.w};
    uint2 uh, ul;
    __nv_bfloat16* hp = (__nv_bfloat16*)&uh;
    __nv_bfloat16* lp = (__nv_bfloat16*)&ul;
    #pragma unroll
    for (int j = 0; j < 4; j++) {
        __nv_bfloat16 h = __float2bfloat16(a[j]);
        hp[j] = h;
        lp[j] = __float2bfloat16(a[j] - __bfloat162float(h));
    }
    ((uint2*)H)[i] = uh;
    ((uint2*)L)[i] = ul;
}

// ---------------- HMMA GEMM, pre-split bf16 inputs, cp.async 3-stage --------
// C[M,N] = (Ah+Al)[M,K] @ (Bh+Bl)[K,N], 3-term split accumulation.
// BM=BN=128, BK=32, 256 threads (8 warps 2x4), warp tile 64x32.
// smem per stage: A hi/lo 2*10240, B hi/lo 2*8704 = 37888 B. 3 stages.
#define PAB 80    // A row pitch bytes (40 halves)
#define PBB 272   // B row pitch bytes (136 halves)
#define STG 37888
#define NSTAGE 3

__device__ __forceinline__ void load_stage(
    uint32_t sb,
    const __nv_bfloat16* __restrict__ Ah, const __nv_bfloat16* __restrict__ Al,
    const __nv_bfloat16* __restrict__ Bh, const __nv_bfloat16* __restrict__ Bl,
    int K, int N, int tid)
{
    // A tile 128x32: 512 16B chunks each for hi/lo. r=idx>>2, c4=idx&3
    #pragma unroll
    for (int it = 0; it < 2; it++) {
        int idx = it * 256 + tid;
        int r = idx >> 2, c4 = idx & 3;
        uint32_t d = sb + r * PAB + c4 * 16;
        const size_t so = (size_t)r * K + c4 * 8;
        cp16(d,         Ah + so);
        cp16(d + 10240, Al + so);
    }
    // B tile 32x128: 512 chunks each. r=idx>>4, c16=idx&15
    #pragma unroll
    for (int it = 0; it < 2; it++) {
        int idx = it * 256 + tid;
        int r = idx >> 4, c16 = idx & 15;
        uint32_t d = sb + 20480 + r * PBB + c16 * 16;
        const size_t so = (size_t)r * N + c16 * 8;
        cp16(d,        Bh + so);
        cp16(d + 8704, Bl + so);
    }
}

template<int EPI>   // 0 plain fp32 out, 1 +bias+relu -> split bf16 out, 2 +bias fp32 out
__global__ __launch_bounds__(256, 1)
void hgemm2_kernel(int M, int N, int K,
                   const __nv_bfloat16* __restrict__ Ah,
                   const __nv_bfloat16* __restrict__ Al,
                   const __nv_bfloat16* __restrict__ Bh,
                   const __nv_bfloat16* __restrict__ Bl,
                   const float* __restrict__ bias,
                   float* __restrict__ C,
                   __nv_bfloat16* __restrict__ Ch,
                   __nv_bfloat16* __restrict__ Cl)
{
    extern __shared__ __align__(16) char smem[];
    uint32_t sb = (uint32_t)__cvta_generic_to_shared(smem);

    int tid  = threadIdx.x;
    int lane = tid & 31;
    int warp = tid >> 5;
    int wm = warp & 1;
    int wn = warp >> 1;
    int row0 = blockIdx.y * 128;
    int col0 = blockIdx.x * 128;

    const __nv_bfloat16* Ahb = Ah + (size_t)row0 * K;
    const __nv_bfloat16* Alb = Al + (size_t)row0 * K;
    const __nv_bfloat16* Bhb = Bh + col0;
    const __nv_bfloat16* Blb = Bl + col0;

    float acc[4][4][4];
    #pragma unroll
    for (int i = 0; i < 4; i++)
        #pragma unroll
        for (int j = 0; j < 4; j++)
            #pragma unroll
            for (int c = 0; c < 4; c++) acc[i][j][c] = 0.f;

    int NT = K / 32;

    // prologue: stages 0..NSTAGE-2
    #pragma unroll
    for (int i = 0; i < NSTAGE - 1; i++) {
        load_stage(sb + i * STG, Ahb + i * 32, Alb + i * 32,
                   Bhb + (size_t)(i * 32) * N, Blb + (size_t)(i * 32) * N, K, N, tid);
        CP_COMMIT();
    }

    for (int kt = 0; kt < NT; kt++) {
        CP_WAIT1();
        __syncthreads();

        int nk = kt + NSTAGE - 1;
        if (nk < NT) {
            uint32_t nb = sb + (nk % NSTAGE) * STG;
            load_stage(nb, Ahb + nk * 32, Alb + nk * 32,
                       Bhb + (size_t)(nk * 32) * N, Blb + (size_t)(nk * 32) * N, K, N, tid);
        }
        CP_COMMIT();

        uint32_t st = sb + (kt % NSTAGE) * STG;
        #pragma unroll
        for (int kk = 0; kk < 32; kk += 16) {
            uint32_t ahi[4][4], alo[4][4], bhi[4][2], blo[4][2];

            #pragma unroll
            for (int mi = 0; mi < 4; mi++) {
                int r = wm * 64 + mi * 16 + (lane & 15);
                int c = kk + (lane >> 4) * 8;
                uint32_t ah = st + r * PAB + c * 2;
                LDSM_X4(ahi[mi][0], ahi[mi][1], ahi[mi][2], ahi[mi][3], ah);
                LDSM_X4(alo[mi][0], alo[mi][1], alo[mi][2], alo[mi][3], ah + 10240);
            }
            #pragma unroll
            for (int nb2 = 0; nb2 < 2; nb2++) {
                int r = kk + (lane & 15);
                int c = wn * 32 + nb2 * 16 + (lane >> 4) * 8;
                uint32_t bh = st + 20480 + r * PBB + c * 2;
                LDSM_X4_T(bhi[nb2*2][0], bhi[nb2*2][1], bhi[nb2*2+1][0], bhi[nb2*2+1][1], bh);
                LDSM_X4_T(blo[nb2*2][0], blo[nb2*2][1], blo[nb2*2+1][0], blo[nb2*2+1][1], bh + 8704);
            }

            #pragma unroll
            for (int mi = 0; mi < 4; mi++)
                #pragma unroll
                for (int ni = 0; ni < 4; ni++) {
                    MMA16816(acc[mi][ni], ahi[mi][0], ahi[mi][1], ahi[mi][2], ahi[mi][3],
                             bhi[ni][0], bhi[ni][1]);
                    MMA16816(acc[mi][ni], ahi[mi][0], ahi[mi][1], ahi[mi][2], ahi[mi][3],
                             blo[ni][0], blo[ni][1]);
                    MMA16816(acc[mi][ni], alo[mi][0], alo[mi][1], alo[mi][2], alo[mi][3],
                             bhi[ni][0], bhi[ni][1]);
                }
        }
    }

    // epilogue
    int g = lane >> 2, t = lane & 3;
    #pragma unroll
    for (int mi = 0; mi < 4; mi++) {
        #pragma unroll
        for (int ni = 0; ni < 4; ni++) {
            int r = row0 + wm * 64 + mi * 16 + g;
            int c = col0 + wn * 32 + ni * 8 + t * 2;
            float v0 = acc[mi][ni][0], v1 = acc[mi][ni][1];
            float v2 = acc[mi][ni][2], v3 = acc[mi][ni][3];
            if (EPI >= 1) {
                float bz0 = bias[c], bz1 = bias[c + 1];
                v0 += bz0; v1 += bz1; v2 += bz0; v3 += bz1;
            }
            if (EPI == 1) {
                v0 = fmaxf(v0, 0.f); v1 = fmaxf(v1, 0.f);
                v2 = fmaxf(v2, 0.f); v3 = fmaxf(v3, 0.f);
                // write split bf16
                float h0 = __bfloat162float(__float2bfloat16(v0));
                float h1 = __bfloat162float(__float2bfloat16(v1));
                float h2 = __bfloat162float(__float2bfloat16(v2));
                float h3 = __bfloat162float(__float2bfloat16(v3));
                *(uint32_t*)&Ch[(size_t)r * N + c]       = pack_bf2(h0, h1);
                *(uint32_t*)&Ch[(size_t)(r + 8) * N + c] = pack_bf2(h2, h3);
                *(uint32_t*)&Cl[(size_t)r * N + c]       = pack_bf2(v0 - h0, v1 - h1);
                *(uint32_t*)&Cl[(size_t)(r + 8) * N + c] = pack_bf2(v2 - h2, v3 - h3);
            } else {
                *(float2*)&C[(size_t)r * N + c]       = make_float2(v0, v1);
                *(float2*)&C[(size_t)(r + 8) * N + c] = make_float2(v2, v3);
            }
        }
    }
}

// ---------------- tensor-core flash attention --------------------------------
// outputs attn result as bf16 hi/lo split (consumed by Wo GEMM)
#define APAD 72

__global__ __launch_bounds__(128)
void attn_mma_kernel(const float* __restrict__ Q,
                     const float* __restrict__ K,
                     const float* __restrict__ V,
                     const int*   __restrict__ vlen,
                     __nv_bfloat16* __restrict__ Oh,
                     __nv_bfloat16* __restrict__ Ol)
{
    __shared__ __align__(16) __nv_bfloat16 Ks_hi[64 * APAD];
    __shared__ __align__(16) __nv_bfloat16 Ks_lo[64 * APAD];
    __shared__ __align__(16) __nv_bfloat16 Vs_hi[64 * APAD];
    __shared__ __align__(16) __nv_bfloat16 Vs_lo[64 * APAD];

    int tid  = threadIdx.x;
    int lane = tid & 31;
    int warp = tid >> 5;
    int g    = lane >> 2;
    int t    = lane & 3;

    int bh = blockIdx.y;
    int b  = bh >> 4;
    int h  = bh & 15;
    int q0 = blockIdx.x * 64;
    int vl = vlen[b];

    const float* Qb = Q + (size_t)(b * SS) * DD + h * HD;
    const float* Kb = K + (size_t)(b * SS) * DD + h * HD;
    const float* Vb = V + (size_t)(b * SS) * DD + h * HD;

    #pragma unroll
    for (int it = 0; it < 8; it++) {
        int idx = it * 128 + tid;
        int r = idx >> 4, c = (idx & 15) * 4;
        float4 v = *(const float4*)(Qb + (size_t)(q0 + r) * DD + c);
        float vv[4] = {v.x, v.y, v.z, v.w};
        #pragma unroll
        for (int j = 0; j < 4; j++) {
            __nv_bfloat16 hi = __float2bfloat16(vv[j]);
            Ks_hi[r * APAD + c + j] = hi;
            Ks_lo[r * APAD + c + j] = __float2bfloat16(vv[j] - __bfloat162float(hi));
        }
    }
    __syncthreads();

    uint32_t qh[4][4], ql[4][4];
    #pragma unroll
    for (int kk = 0; kk < 4; kk++) {
        int r = warp * 16 + (lane & 15);
        int c = kk * 16 + (lane >> 4) * 8;
        uint32_t ah = (uint32_t)__cvta_generic_to_shared(&Ks_hi[r * APAD + c]);
        uint32_t al = (uint32_t)__cvta_generic_to_shared(&Ks_lo[r * APAD + c]);
        LDSM_X4(qh[kk][0], qh[kk][1], qh[kk][2], qh[kk][3], ah);
        LDSM_X4(ql[kk][0], ql[kk][1], ql[kk][2], ql[kk][3], al);
    }

    float o[8][4];
    #pragma unroll
    for (int i = 0; i < 8; i++)
        #pragma unroll
        for (int c = 0; c < 4; c++) o[i][c] = 0.f;
    float m0 = -1e30f, m1 = -1e30f, l0 = 0.f, l1 = 0.f;

    int nkt = (vl + 63) >> 6;
    for (int kt = 0; kt < nkt; kt++) {
        int k0 = kt * 64;
        __syncthreads();

        #pragma unroll
        for (int it = 0; it < 8; it++) {
            int idx = it * 128 + tid;
            int r = idx >> 4, c = (idx & 15) * 4;
            float4 kv = *(const float4*)(Kb + (size_t)(k0 + r) * DD + c);
            float4 vv = *(const float4*)(Vb + (size_t)(k0 + r) * DD + c);
            float ka[4] = {kv.x, kv.y, kv.z, kv.w};
            float va[4] = {vv.x, vv.y, vv.z, vv.w};
            #pragma unroll
            for (int j = 0; j < 4; j++) {
                __nv_bfloat16 hi = __float2bfloat16(ka[j]);
                Ks_hi[r * APAD + c + j] = hi;
                Ks_lo[r * APAD + c + j] = __float2bfloat16(ka[j] - __bfloat162float(hi));
                __nv_bfloat16 vh = __float2bfloat16(va[j]);
                Vs_hi[r * APAD + c + j] = vh;
                Vs_lo[r * APAD + c + j] = __float2bfloat16(va[j] - __bfloat162float(vh));
            }
        }
        __syncthreads();

        float s[8][4];
        #pragma unroll
        for (int i = 0; i < 8; i++)
            #pragma unroll
            for (int c = 0; c < 4; c++) s[i][c] = 0.f;

        #pragma unroll
        for (int kk = 0; kk < 4; kk++) {
            #pragma unroll
            for (int nb = 0; nb < 4; nb++) {
                int r = nb * 16 + (lane & 15);
                int c = kk * 16 + (lane >> 4) * 8;
                uint32_t kha = (uint32_t)__cvta_generic_to_shared(&Ks_hi[r * APAD + c]);
                uint32_t kla = (uint32_t)__cvta_generic_to_shared(&Ks_lo[r * APAD + c]);
                uint32_t kh0, kh1, kh2, kh3, kl0, kl1, kl2, kl3;
                LDSM_X4(kh0, kh1, kh2, kh3, kha);
                LDSM_X4(kl0, kl1, kl2, kl3, kla);
                MMA16816(s[2*nb],   qh[kk][0], qh[kk][1], qh[kk][2], qh[kk][3], kh0, kh2);
                MMA16816(s[2*nb],   qh[kk][0], qh[kk][1], qh[kk][2], qh[kk][3], kl0, kl2);
                MMA16816(s[2*nb],   ql[kk][0], ql[kk][1], ql[kk][2], ql[kk][3], kh0, kh2);
                MMA16816(s[2*nb+1], qh[kk][0], qh[kk][1], qh[kk][2], qh[kk][3], kh1, kh3);
                MMA16816(s[2*nb+1], qh[kk][0], qh[kk][1], qh[kk][2], qh[kk][3], kl1, kl3);
                MMA16816(s[2*nb+1], ql[kk][0], ql[kk][1], ql[kk][2], ql[kk][3], kh1, kh3);
            }
        }

        #pragma unroll
        for (int nb = 0; nb < 8; nb++) {
            int c0 = k0 + nb * 8 + 2 * t;
            int c1 = c0 + 1;
            s[nb][0] = (c0 < vl) ? s[nb][0] * 0.125f : -1e30f;
            s[nb][1] = (c1 < vl) ? s[nb][1] * 0.125f : -1e30f;
            s[nb][2] = (c0 < vl) ? s[nb][2] * 0.125f : -1e30f;
            s[nb][3] = (c1 < vl) ? s[nb][3] * 0.125f : -1e30f;
        }

        float tm0 = -1e30f, tm1 = -1e30f;
        #pragma unroll
        for (int nb = 0; nb < 8; nb++) {
            tm0 = fmaxf(tm0, fmaxf(s[nb][0], s[nb][1]));
            tm1 = fmaxf(tm1, fmaxf(s[nb][2], s[nb][3]));
        }
        tm0 = fmaxf(tm0, __shfl_xor_sync(0xffffffffu, tm0, 1));
        tm0 = fmaxf(tm0, __shfl_xor_sync(0xffffffffu, tm0, 2));
        tm1 = fmaxf(tm1, __shfl_xor_sync(0xffffffffu, tm1, 1));
        tm1 = fmaxf(tm1, __shfl_xor_sync(0xffffffffu, tm1, 2));

        float mn0 = fmaxf(m0, tm0);
        float mn1 = fmaxf(m1, tm1);
        float al0 = expf_fast(m0 - mn0);
        float al1 = expf_fast(m1 - mn1);

        uint32_t pAh[4][4], pAl[4][4];
        float ls0 = 0.f, ls1 = 0.f;
        #pragma unroll
        for (int nb = 0; nb < 8; nb++) {
            float p0 = expf_fast(s[nb][0] - mn0);
            float p1 = expf_fast(s[nb][1] - mn0);
            float p2 = expf_fast(s[nb][2] - mn1);
            float p3 = expf_fast(s[nb][3] - mn1);
            ls0 += p0 + p1;
            ls1 += p2 + p3;
            float h0 = __bfloat162float(__float2bfloat16(p0));
            float h1 = __bfloat162float(__float2bfloat16(p1));
            float h2 = __bfloat162float(__float2bfloat16(p2));
            float h3 = __bfloat162float(__float2bfloat16(p3));
            int ks = nb >> 1;
            int hf = (nb & 1) * 2;
            pAh[ks][hf + 0] = pack_bf2(h0, h1);
            pAh[ks][hf + 1] = pack_bf2(h2, h3);
            pAl[ks][hf + 0] = pack_bf2(p0 - h0, p1 - h1);
            pAl[ks][hf + 1] = pack_bf2(p2 - h2, p3 - h3);
        }
        ls0 += __shfl_xor_sync(0xffffffffu, ls0, 1);
        ls0 += __shfl_xor_sync(0xffffffffu, ls0, 2);
        ls1 += __shfl_xor_sync(0xffffffffu, ls1, 1);
        ls1 += __shfl_xor_sync(0xffffffffu, ls1, 2);

        l0 = l0 * al0 + ls0;
        l1 = l1 * al1 + ls1;
        m0 = mn0;
        m1 = mn1;

        #pragma unroll
        for (int nb = 0; nb < 8; nb++) {
            o[nb][0] *= al0; o[nb][1] *= al0;
            o[nb][2] *= al1; o[nb][3] *= al1;
        }

        #pragma unroll
        for (int kk = 0; kk < 4; kk++) {
            uint32_t a0h = pAh[kk][0], a1h = pAh[kk][1], a2h = pAh[kk][2], a3h = pAh[kk][3];
            uint32_t a0l = pAl[kk][0], a1l = pAl[kk][1], a2l = pAl[kk][2], a3l = pAl[kk][3];
            #pragma unroll
            for (int nb = 0; nb < 4; nb++) {
                int r = kk * 16 + (lane & 15);
                int c = nb * 16 + (lane >> 4) * 8;
                uint32_t vha = (uint32_t)__cvta_generic_to_shared(&Vs_hi[r * APAD + c]);
                uint32_t vla = (uint32_t)__cvta_generic_to_shared(&Vs_lo[r * APAD + c]);
                uint32_t vh0, vh1, vh2, vh3, vl0_, vl1_, vl2_, vl3_;
                LDSM_X4_T(vh0, vh1, vh2, vh3, vha);
                LDSM_X4_T(vl0_, vl1_, vl2_, vl3_, vla);
                MMA16816(o[2*nb],   a0h, a1h, a2h, a3h, vh0, vh1);
                MMA16816(o[2*nb],   a0h, a1h, a2h, a3h, vl0_, vl1_);
                MMA16816(o[2*nb],   a0l, a1l, a2l, a3l, vh0, vh1);
                MMA16816(o[2*nb+1], a0h, a1h, a2h, a3h, vh2, vh3);
                MMA16816(o[2*nb+1], a0h, a1h, a2h, a3h, vl2_, vl3_);
                MMA16816(o[2*nb+1], a0l, a1l, a2l, a3l, vh2, vh3);
            }
        }
    }

    float inv0 = 1.f / l0;
    float inv1 = 1.f / l1;
    int row0g = q0 + warp * 16 + g;
    int row1g = row0g + 8;
    __nv_bfloat16* Ohb = Oh + (size_t)(b * SS) * DD + h * HD;
    __nv_bfloat16* Olb = Ol + (size_t)(b * SS) * DD + h * HD;
    #pragma unroll
    for (int nb = 0; nb < 8; nb++) {
        int col = nb * 8 + 2 * t;
        float v0 = o[nb][0] * inv0, v1 = o[nb][1] * inv0;
        float v2 = o[nb][2] * inv1, v3 = o[nb][3] * inv1;
        float h0 = __bfloat162float(__float2bfloat16(v0));
        float h1 = __bfloat162float(__float2bfloat16(v1));
        float h2 = __bfloat162float(__float2bfloat16(v2));
        float h3 = __bfloat162float(__float2bfloat16(v3));
        *(uint32_t*)(Ohb + (size_t)row0g * DD + col) = pack_bf2(h0, h1);
        *(uint32_t*)(Ohb + (size_t)row1g * DD + col) = pack_bf2(h2, h3);
        *(uint32_t*)(Olb + (size_t)row0g * DD + col) = pack_bf2(v0 - h0, v1 - h1);
        *(uint32_t*)(Olb + (size_t)row1g * DD + col) = pack_bf2(v2 - h2, v3 - h3);
    }
}

// ---------------- fused residual + LayerNorm --------------------------------
// SPLIT=1: additionally emit bf16 hi/lo of the normalized output
template<int SPLIT>
__global__ __launch_bounds__(256)
void ln_kernel(const float* __restrict__ A,
               const float* __restrict__ R,
               const float* __restrict__ g,
               const float* __restrict__ be,
               float* __restrict__ out,
               __nv_bfloat16* __restrict__ oh,
               __nv_bfloat16* __restrict__ ol)
{
    int row = blockIdx.x;
    int t   = threadIdx.x;
    const float4* a4 = (const float4*)(A + (size_t)row * DD);
    const float4* r4 = (const float4*)(R + (size_t)row * DD);
    float4 av = a4[t];
    float4 rv = r4[t];
    float x0 = av.x + rv.x, x1 = av.y + rv.y, x2 = av.z + rv.z, x3 = av.w + rv.w;

    float s = x0 + x1 + x2 + x3;
    float q = x0 * x0 + x1 * x1 + x2 * x2 + x3 * x3;
    #pragma unroll
    for (int off = 16; off >= 1; off >>= 1) {
        s += __shfl_xor_sync(0xffffffffu, s, off);
        q += __shfl_xor_sync(0xffffffffu, q, off);
    }
    __shared__ float rs[8], rq[8];
    int w = t >> 5, lane = t & 31;
    if (lane == 0) { rs[w] = s; rq[w] = q; }
    __syncthreads();
    float tot = 0.f, totq = 0.f;
    #pragma unroll
    for (int i = 0; i < 8; i++) { tot += rs[i]; totq += rq[i]; }

    float mean = tot * (1.f / DD);
    float var  = totq * (1.f / DD) - mean * mean;
    float rstd = rsqrtf(var + EPSL);

    float4 gv = ((const float4*)g)[t];
    float4 bv = ((const float4*)be)[t];
    float4 ov;
    ov.x = (x0 - mean) * rstd * gv.x + bv.x;
    ov.y = (x1 - mean) * rstd * gv.y + bv.y;
    ov.z = (x2 - mean) * rstd * gv.z + bv.z;
    ov.w = (x3 - mean) * rstd * gv.w + bv.w;
    ((float4*)(out + (size_t)row * DD))[t] = ov;

    if (SPLIT) {
        float a[4] = {ov.x, ov.y, ov.z, ov.w};
        uint2 uh, ul;
        __nv_bfloat16* hp = (__nv_bfloat16*)&uh;
        __nv_bfloat16* lp = (__nv_bfloat16*)&ul;
        #pragma unroll
        for (int j = 0; j < 4; j++) {
            __nv_bfloat16 h = __float2bfloat16(a[j]);
            hp[j] = h;
            lp[j] = __float2bfloat16(a[j] - __bfloat162float(h));
        }
        ((uint2*)(oh + (size_t)row * DD))[t] = uh;
        ((uint2*)(ol + (size_t)row * DD))[t] = ul;
    }
}

// ---------------- launch ----------------------------------------------------
extern "C" void kernel_launch(void* const* d_in, const int* in_sizes, int n_in,
                              void* d_out, int out_size)
{
    const float* x   = (const float*)d_in[0];
    const int*   vl  = (const int*)  d_in[1];
    const float* Wq  = (const float*)d_in[2];
    const float* Wk  = (const float*)d_in[3];
    const float* Wv  = (const float*)d_in[4];
    const float* Wo  = (const float*)d_in[5];
    const float* W1  = (const float*)d_in[6];
    const float* b1  = (const float*)d_in[7];
    const float* W2  = (const float*)d_in[8];
    const float* b2  = (const float*)d_in[9];
    const float* g1  = (const float*)d_in[10];
    const float* be1 = (const float*)d_in[11];
    const float* g2  = (const float*)d_in[12];
    const float* be2 = (const float*)d_in[13];
    float* out = (float*)d_out;

    float *q, *k, *v, *r;
    cudaGetSymbolAddress((void**)&q, g_q);
    cudaGetSymbolAddress((void**)&k, g_k);
    cudaGetSymbolAddress((void**)&v, g_v);
    cudaGetSymbolAddress((void**)&r, g_r);

    __nv_bfloat16 *xh,*xl,*ah,*al,*rh,*rl,*ffh,*ffl;
    cudaGetSymbolAddress((void**)&xh, g_xh);   cudaGetSymbolAddress((void**)&xl, g_xl);
    cudaGetSymbolAddress((void**)&ah, g_ah);   cudaGetSymbolAddress((void**)&al, g_al);
    cudaGetSymbolAddress((void**)&rh, g_rh);   cudaGetSymbolAddress((void**)&rl, g_rl);
    cudaGetSymbolAddress((void**)&ffh, g_ffh); cudaGetSymbolAddress((void**)&ffl, g_ffl);

    __nv_bfloat16 *wqh,*wql,*wkh,*wkl,*wvh,*wvl,*woh,*wol,*w1h,*w1l,*w2h,*w2l;
    cudaGetSymbolAddress((void**)&wqh, g_wqh); cudaGetSymbolAddress((void**)&wql, g_wql);
    cudaGetSymbolAddress((void**)&wkh, g_wkh); cudaGetSymbolAddress((void**)&wkl, g_wkl);
    cudaGetSymbolAddress((void**)&wvh, g_wvh); cudaGetSymbolAddress((void**)&wvl, g_wvl);
    cudaGetSymbolAddress((void**)&woh, g_woh); cudaGetSymbolAddress((void**)&wol, g_wol);
    cudaGetSymbolAddress((void**)&w1h, g_w1h); cudaGetSymbolAddress((void**)&w1l, g_w1l);
    cudaGetSymbolAddress((void**)&w2h, g_w2h); cudaGetSymbolAddress((void**)&w2l, g_w2l);

    int gemm_smem = NSTAGE * STG;   // 113664
    cudaFuncSetAttribute(hgemm2_kernel<0>, cudaFuncAttributeMaxDynamicSharedMemorySize, gemm_smem);
    cudaFuncSetAttribute(hgemm2_kernel<1>, cudaFuncAttributeMaxDynamicSharedMemorySize, gemm_smem);
    cudaFuncSetAttribute(hgemm2_kernel<2>, cudaFuncAttributeMaxDynamicSharedMemorySize, gemm_smem);

    // pre-split weights + input
    wsplit_kernel<<<DD*DD/1024, 256>>>(Wq, wqh, wql);
    wsplit_kernel<<<DD*DD/1024, 256>>>(Wk, wkh, wkl);
    wsplit_kernel<<<DD*DD/1024, 256>>>(Wv, wvh, wvl);
    wsplit_kernel<<<DD*DD/1024, 256>>>(Wo, woh, wol);
    wsplit_kernel<<<DD*FF/1024, 256>>>(W1, w1h, w1l);
    wsplit_kernel<<<DD*FF/1024, 256>>>(W2, w2h, w2l);
    wsplit_kernel<<<NR*DD/1024, 256>>>(x,  xh,  xl);

    dim3 gD(DD / 128, NR / 128);     // (8, 64)
    dim3 gF(FF / 128, NR / 128);     // (32, 64)

    // QKV projections
    hgemm2_kernel<0><<<gD, 256, gemm_smem>>>(NR, DD, DD, xh, xl, wqh, wql, nullptr, q, nullptr, nullptr);
    hgemm2_kernel<0><<<gD, 256, gemm_smem>>>(NR, DD, DD, xh, xl, wkh, wkl, nullptr, k, nullptr, nullptr);
    hgemm2_kernel<0><<<gD, 256, gemm_smem>>>(NR, DD, DD, xh, xl, wvh, wvl, nullptr, v, nullptr, nullptr);

    // attention -> split output
    attn_mma_kernel<<<dim3(SS / 64, BB * HH), 128>>>(q, k, v, vl, ah, al);

    // output projection (reads split attn out) -> q fp32
    hgemm2_kernel<0><<<gD, 256, gemm_smem>>>(NR, DD, DD, ah, al, woh, wol, nullptr, q, nullptr, nullptr);

    // residual + LN1 -> r fp32 + split
    ln_kernel<1><<<NR, 256>>>(q, x, g1, be1, r, rh, rl);

    // FFN: FF1 emits split directly; FF2 -> k fp32
    hgemm2_kernel<1><<<gF, 256, gemm_smem>>>(NR, FF, DD, rh, rl, w1h, w1l, b1, nullptr, ffh, ffl);
    hgemm2_kernel<2><<<gD, 256, gemm_smem>>>(NR, DD, FF, ffh, ffl, w2h, w2l, b2, k, nullptr, nullptr);

    // residual + LN2 -> output
    ln_kernel<0><<<NR, 256>>>(k, r, g2, be2, out, nullptr, nullptr);
}

// round 7
// speedup vs baseline: 3.9234x; 1.5440x over previous
#include <cuda_runtime.h>
#include <cuda_fp16.h>
#include <math.h>
#include <stdint.h>

// Problem constants
#define BB   4
#define SS   2048
#define DD   1024
#define HH   16
#define HD   64
#define FF   4096
#define NR   (BB*SS)          // 8192 rows
#define EPSL 1e-5f

// ---------------- scratch (device globals; no allocation allowed) ----------
__device__ float g_q [NR*DD];        // Wo output
__device__ float g_k [NR*DD];        // FF2 output
__device__ float g_r [NR*DD];        // LN1 output fp32

// fp16 activations
__device__ __align__(16) __half g_xh [NR*DD], g_xl [NR*DD];
__device__ __align__(16) __half g_qh [NR*DD], g_ql [NR*DD];
__device__ __align__(16) __half g_kvh[NR*DD], g_vvh[NR*DD];
__device__ __align__(16) __half g_ah [NR*DD], g_al [NR*DD];
__device__ __align__(16) __half g_rh [NR*DD], g_rl [NR*DD];
__device__ __align__(16) __half g_ffh[(size_t)NR*FF], g_ffl[(size_t)NR*FF];

// fp16 weights (hi only). QKV concatenated along N: [DD, 3*DD]
__device__ __align__(16) __half g_wqkv[DD*3*DD];
__device__ __align__(16) __half g_wo  [DD*DD];
__device__ __align__(16) __half g_w1  [(size_t)DD*FF];
__device__ __align__(16) __half g_w2  [(size_t)DD*FF];

// ---------------- asm helpers ------------------------------------------------
#define LDSM_X4(R0,R1,R2,R3,ADDR) \
    asm volatile("ldmatrix.sync.aligned.m8n8.x4.shared.b16 {%0,%1,%2,%3},[%4];" \
        : "=r"(R0),"=r"(R1),"=r"(R2),"=r"(R3) : "r"(ADDR))

#define LDSM_X4_T(R0,R1,R2,R3,ADDR) \
    asm volatile("ldmatrix.sync.aligned.m8n8.x4.trans.shared.b16 {%0,%1,%2,%3},[%4];" \
        : "=r"(R0),"=r"(R1),"=r"(R2),"=r"(R3) : "r"(ADDR))

#define MMAH(D,A0,A1,A2,A3,B0,B1) \
    asm volatile("mma.sync.aligned.m16n8k16.row.col.f32.f16.f16.f32 " \
        "{%0,%1,%2,%3},{%4,%5,%6,%7},{%8,%9},{%0,%1,%2,%3};" \
        : "+f"(D[0]),"+f"(D[1]),"+f"(D[2]),"+f"(D[3]) \
        : "r"(A0),"r"(A1),"r"(A2),"r"(A3),"r"(B0),"r"(B1))

__device__ __forceinline__ void cp16(uint32_t dst, const void* src) {
    asm volatile("cp.async.cg.shared.global [%0],[%1],16;" :: "r"(dst), "l"(src));
}
#define CP_COMMIT() asm volatile("cp.async.commit_group;" ::: "memory")
#define CP_WAIT0()  asm volatile("cp.async.wait_group 0;" ::: "memory")
#define CP_WAIT1()  asm volatile("cp.async.wait_group 1;" ::: "memory")

__device__ __forceinline__ uint32_t pack_h2(float a, float b) {
    __half2 h = __floats2half2_rn(a, b);
    return *reinterpret_cast<uint32_t*>(&h);
}

// fast exp on the FMA pipe. x <= 0 expected. ~2e-6 rel err.
__device__ __forceinline__ float expf_fast(float x) {
    float y = fmaxf(x * 1.44269504088896f, -126.f);
    float fl = floorf(y);
    float f = y - fl;
    float p = 1.54653240e-4f;
    p = fmaf(p, f, 1.33335581e-3f);
    p = fmaf(p, f, 9.61812910e-3f);
    p = fmaf(p, f, 5.55041086e-2f);
    p = fmaf(p, f, 2.40226507e-1f);
    p = fmaf(p, f, 6.93147181e-1f);
    p = fmaf(p, f, 1.0f);
    int ei = (int)fl;
    float sc = __int_as_float((ei + 127) << 23);
    return p * sc;
}

// ---------------- one-shot fp32 -> fp16 (hi[,lo]) split, all tensors ---------
struct SplitSeg {
    const float* src;
    __half* h;
    __half* l;        // nullptr -> hi only
    int nblk;         // blocks of 1024 elems
    int cols;         // source row length
    int stride;       // dst row stride
    int off;          // dst column offset
};
struct SplitArgs { SplitSeg s[7]; };

__global__ __launch_bounds__(256)
void split_all_kernel(SplitArgs a)
{
    int blk = blockIdx.x;
    int i = 0;
    while (blk >= a.s[i].nblk) { blk -= a.s[i].nblk; i++; }
    SplitSeg sg = a.s[i];

    int e   = blk * 1024 + threadIdx.x * 4;
    int row = e / sg.cols;
    int col = e - row * sg.cols;
    size_t d = (size_t)row * sg.stride + sg.off + col;

    float4 v = *(const float4*)(sg.src + (size_t)e);
    float av[4] = {v.x, v.y, v.z, v.w};
    uint2 uh, ul;
    __half* hp = (__half*)&uh;
    __half* lp = (__half*)&ul;
    #pragma unroll
    for (int j = 0; j < 4; j++) {
        __half h = __float2half_rn(av[j]);
        hp[j] = h;
        lp[j] = __float2half_rn(av[j] - __half2float(h));
    }
    *(uint2*)(sg.h + d) = uh;
    if (sg.l) *(uint2*)(sg.l + d) = ul;
}

// ---------------- HMMA GEMM, 2-term fp16 split, cp.async 3-stage -------------
// C[M,N] = (Ah+Al)[M,K] @ Bh[K,N]
// BM=BN=128, BK=32, 256 threads (8 warps 2x4), warp tile 64x32.
// stage: Ah 10240 + Al 10240 + Bh 8704 = 29184 B, 3 stages.
#define PAB 80
#define PBB 272
#define STG3 29184
#define NST 3

__device__ __forceinline__ void load_stage3(
    uint32_t sb,
    const __half* __restrict__ Ah, const __half* __restrict__ Al,
    const __half* __restrict__ Bh, int K, int N, int tid)
{
    #pragma unroll
    for (int it = 0; it < 2; it++) {
        int idx = it * 256 + tid;
        int r = idx >> 2, c4 = idx & 3;
        uint32_t d = sb + r * PAB + c4 * 16;
        size_t so = (size_t)r * K + c4 * 8;
        cp16(d,         Ah + so);
        cp16(d + 10240, Al + so);
    }
    #pragma unroll
    for (int it = 0; it < 2; it++) {
        int idx = it * 256 + tid;
        int r = idx >> 4, c16 = idx & 15;
        cp16(sb + 20480 + r * PBB + c16 * 16, Bh + (size_t)r * N + c16 * 8);
    }
}

// EPI: 0 plain fp32 | 1 bias+relu -> split fp16 | 2 bias -> fp32 | 3 QKV fused
template<int EPI>
__global__ __launch_bounds__(256)
void hgemm3_kernel(int M, int N, int K,
                   const __half* __restrict__ Ah,
                   const __half* __restrict__ Al,
                   const __half* __restrict__ Bh,
                   const float* __restrict__ bias,
                   float* __restrict__ C,
                   __half* __restrict__ Ch,
                   __half* __restrict__ Cl,
                   __half* __restrict__ Ko,
                   __half* __restrict__ Vo)
{
    extern __shared__ __align__(16) char smem[];
    uint32_t sb = (uint32_t)__cvta_generic_to_shared(smem);

    int tid  = threadIdx.x;
    int lane = tid & 31;
    int warp = tid >> 5;
    int wm = warp & 1;
    int wn = warp >> 1;
    int row0 = blockIdx.y * 128;
    int col0 = blockIdx.x * 128;

    const __half* Ahb = Ah + (size_t)row0 * K;
    const __half* Alb = Al + (size_t)row0 * K;
    const __half* Bhb = Bh + col0;

    float acc[4][4][4];
    #pragma unroll
    for (int i = 0; i < 4; i++)
        #pragma unroll
        for (int j = 0; j < 4; j++)
            #pragma unroll
            for (int c = 0; c < 4; c++) acc[i][j][c] = 0.f;

    int NT = K / 32;

    #pragma unroll
    for (int i = 0; i < NST - 1; i++) {
        load_stage3(sb + i * STG3, Ahb + i * 32, Alb + i * 32,
                    Bhb + (size_t)(i * 32) * N, K, N, tid);
        CP_COMMIT();
    }

    for (int kt = 0; kt < NT; kt++) {
        CP_WAIT1();
        __syncthreads();

        int nk = kt + NST - 1;
        if (nk < NT) {
            load_stage3(sb + (nk % NST) * STG3, Ahb + nk * 32, Alb + nk * 32,
                        Bhb + (size_t)(nk * 32) * N, K, N, tid);
        }
        CP_COMMIT();

        uint32_t st = sb + (kt % NST) * STG3;
        #pragma unroll
        for (int kk = 0; kk < 32; kk += 16) {
            uint32_t ahi[4][4], alo[4][4], bfr[4][2];

            #pragma unroll
            for (int mi = 0; mi < 4; mi++) {
                int r = wm * 64 + mi * 16 + (lane & 15);
                int c = kk + (lane >> 4) * 8;
                uint32_t ah = st + r * PAB + c * 2;
                LDSM_X4(ahi[mi][0], ahi[mi][1], ahi[mi][2], ahi[mi][3], ah);
                LDSM_X4(alo[mi][0], alo[mi][1], alo[mi][2], alo[mi][3], ah + 10240);
            }
            #pragma unroll
            for (int nb2 = 0; nb2 < 2; nb2++) {
                int r = kk + (lane & 15);
                int c = wn * 32 + nb2 * 16 + (lane >> 4) * 8;
                uint32_t bh = st + 20480 + r * PBB + c * 2;
                LDSM_X4_T(bfr[nb2*2][0], bfr[nb2*2][1], bfr[nb2*2+1][0], bfr[nb2*2+1][1], bh);
            }

            #pragma unroll
            for (int mi = 0; mi < 4; mi++)
                #pragma unroll
                for (int ni = 0; ni < 4; ni++) {
                    MMAH(acc[mi][ni], ahi[mi][0], ahi[mi][1], ahi[mi][2], ahi[mi][3],
                         bfr[ni][0], bfr[ni][1]);
                    MMAH(acc[mi][ni], alo[mi][0], alo[mi][1], alo[mi][2], alo[mi][3],
                         bfr[ni][0], bfr[ni][1]);
                }
        }
    }

    // epilogue
    int g = lane >> 2, t = lane & 3;
    int region = col0 >> 10;         // EPI 3 only
    int lc0 = col0 & 1023;
    #pragma unroll
    for (int mi = 0; mi < 4; mi++) {
        #pragma unroll
        for (int ni = 0; ni < 4; ni++) {
            int r = row0 + wm * 64 + mi * 16 + g;
            int cc = wn * 32 + ni * 8 + t * 2;
            float v0 = acc[mi][ni][0], v1 = acc[mi][ni][1];
            float v2 = acc[mi][ni][2], v3 = acc[mi][ni][3];

            if (EPI == 1 || EPI == 2) {
                int c = col0 + cc;
                float bz0 = bias[c], bz1 = bias[c + 1];
                v0 += bz0; v1 += bz1; v2 += bz0; v3 += bz1;
            }
            if (EPI == 1) {
                v0 = fmaxf(v0, 0.f); v1 = fmaxf(v1, 0.f);
                v2 = fmaxf(v2, 0.f); v3 = fmaxf(v3, 0.f);
            }

            if (EPI == 0 || EPI == 2) {
                int c = col0 + cc;
                *(float2*)&C[(size_t)r * N + c]       = make_float2(v0, v1);
                *(float2*)&C[(size_t)(r + 8) * N + c] = make_float2(v2, v3);
            } else if (EPI == 1) {
                int c = col0 + cc;
                float h0 = __half2float(__float2half_rn(v0));
                float h1 = __half2float(__float2half_rn(v1));
                float h2 = __half2float(__float2half_rn(v2));
                float h3 = __half2float(__float2half_rn(v3));
                *(uint32_t*)&Ch[(size_t)r * N + c]       = pack_h2(h0, h1);
                *(uint32_t*)&Ch[(size_t)(r + 8) * N + c] = pack_h2(h2, h3);
                *(uint32_t*)&Cl[(size_t)r * N + c]       = pack_h2(v0 - h0, v1 - h1);
                *(uint32_t*)&Cl[(size_t)(r + 8) * N + c] = pack_h2(v2 - h2, v3 - h3);
            } else {   // EPI == 3
                int lc = lc0 + cc;
                if (region == 0) {
                    float h0 = __half2float(__float2half_rn(v0));
                    float h1 = __half2float(__float2half_rn(v1));
                    float h2 = __half2float(__float2half_rn(v2));
                    float h3 = __half2float(__float2half_rn(v3));
                    *(uint32_t*)&Ch[(size_t)r * DD + lc]       = pack_h2(h0, h1);
                    *(uint32_t*)&Ch[(size_t)(r + 8) * DD + lc] = pack_h2(h2, h3);
                    *(uint32_t*)&Cl[(size_t)r * DD + lc]       = pack_h2(v0 - h0, v1 - h1);
                    *(uint32_t*)&Cl[(size_t)(r + 8) * DD + lc] = pack_h2(v2 - h2, v3 - h3);
                } else {
                    __half* KV = (region == 1) ? Ko : Vo;
                    *(uint32_t*)&KV[(size_t)r * DD + lc]       = pack_h2(v0, v1);
                    *(uint32_t*)&KV[(size_t)(r + 8) * DD + lc] = pack_h2(v2, v3);
                }
            }
        }
    }
}

// ---------------- flash attention: pre-split fp16, cp.async, 2-term ----------
// smem: two 18432B KV buffers (K at +0, V at +9216), pitch 144B.
__device__ __forceinline__ void load_kv(uint32_t buf,
                                        const __half* __restrict__ KhB,
                                        const __half* __restrict__ VhB,
                                        int k0, int tid)
{
    #pragma unroll
    for (int it = 0; it < 4; it++) {
        int idx = it * 128 + tid;
        int r = idx >> 3, c = idx & 7;
        cp16(buf + r * 144 + c * 16,        KhB + (size_t)(k0 + r) * DD + c * 8);
        cp16(buf + 9216 + r * 144 + c * 16, VhB + (size_t)(k0 + r) * DD + c * 8);
    }
}

__global__ __launch_bounds__(128)
void attn_f16_kernel(const __half* __restrict__ Qh, const __half* __restrict__ Ql,
                     const __half* __restrict__ Kh, const __half* __restrict__ Vh,
                     const int* __restrict__ vlen,
                     __half* __restrict__ Oh, __half* __restrict__ Ol)
{
    __shared__ __align__(16) char smem[36864];
    uint32_t sb = (uint32_t)__cvta_generic_to_shared(smem);

    int tid  = threadIdx.x;
    int lane = tid & 31;
    int warp = tid >> 5;
    int g    = lane >> 2;
    int t    = lane & 3;

    int bh = blockIdx.y;
    int b  = bh >> 4;
    int h  = bh & 15;
    int q0 = blockIdx.x * 64;
    int vl = vlen[b];

    size_t base = (size_t)(b * SS) * DD + h * HD;
    const __half* QhB = Qh + base + (size_t)q0 * DD;
    const __half* QlB = Ql + base + (size_t)q0 * DD;
    const __half* KhB = Kh + base;
    const __half* VhB = Vh + base;

    // stage Q (hi at sb, lo at sb+9216)
    #pragma unroll
    for (int it = 0; it < 4; it++) {
        int idx = it * 128 + tid;
        int r = idx >> 3, c = idx & 7;
        cp16(sb + r * 144 + c * 16,        QhB + (size_t)r * DD + c * 8);
        cp16(sb + 9216 + r * 144 + c * 16, QlB + (size_t)r * DD + c * 8);
    }
    CP_COMMIT(); CP_WAIT0();
    __syncthreads();

    uint32_t qh[4][4], ql[4][4];
    #pragma unroll
    for (int kk = 0; kk < 4; kk++) {
        int r = warp * 16 + (lane & 15);
        int c = kk * 16 + (lane >> 4) * 8;
        LDSM_X4(qh[kk][0], qh[kk][1], qh[kk][2], qh[kk][3], sb + r * 144 + c * 2);
        LDSM_X4(ql[kk][0], ql[kk][1], ql[kk][2], ql[kk][3], sb + 9216 + r * 144 + c * 2);
    }
    __syncthreads();    // Q frags read; buffer 0 reusable

    float o[8][4];
    #pragma unroll
    for (int i = 0; i < 8; i++)
        #pragma unroll
        for (int c = 0; c < 4; c++) o[i][c] = 0.f;
    float m0 = -1e30f, m1 = -1e30f, l0 = 0.f, l1 = 0.f;

    int nkt = (vl + 63) >> 6;

    load_kv(sb, KhB, VhB, 0, tid);
    CP_COMMIT();

    for (int kt = 0; kt < nkt; kt++) {
        __syncthreads();     // compute of kt-1 done before overwriting its buffer
        if (kt + 1 < nkt)
            load_kv(sb + ((kt + 1) & 1) * 18432, KhB, VhB, (kt + 1) * 64, tid);
        CP_COMMIT();
        CP_WAIT1();
        __syncthreads();     // tile kt resident for all warps

        uint32_t cur = sb + (kt & 1) * 18432;
        int k0 = kt * 64;

        // S = (Qh+Ql) Kh^T
        float s[8][4];
        #pragma unroll
        for (int i = 0; i < 8; i++)
            #pragma unroll
            for (int c = 0; c < 4; c++) s[i][c] = 0.f;

        #pragma unroll
        for (int kk = 0; kk < 4; kk++) {
            #pragma unroll
            for (int nb = 0; nb < 4; nb++) {
                int r = nb * 16 + (lane & 15);
                int c = kk * 16 + (lane >> 4) * 8;
                uint32_t ka = cur + r * 144 + c * 2;
                uint32_t kh0, kh1, kh2, kh3;
                LDSM_X4(kh0, kh1, kh2, kh3, ka);
                MMAH(s[2*nb],   qh[kk][0], qh[kk][1], qh[kk][2], qh[kk][3], kh0, kh2);
                MMAH(s[2*nb],   ql[kk][0], ql[kk][1], ql[kk][2], ql[kk][3], kh0, kh2);
                MMAH(s[2*nb+1], qh[kk][0], qh[kk][1], qh[kk][2], qh[kk][3], kh1, kh3);
                MMAH(s[2*nb+1], ql[kk][0], ql[kk][1], ql[kk][2], ql[kk][3], kh1, kh3);
            }
        }

        // scale + mask
        #pragma unroll
        for (int nb = 0; nb < 8; nb++) {
            int c0 = k0 + nb * 8 + 2 * t;
            int c1 = c0 + 1;
            s[nb][0] = (c0 < vl) ? s[nb][0] * 0.125f : -1e30f;
            s[nb][1] = (c1 < vl) ? s[nb][1] * 0.125f : -1e30f;
            s[nb][2] = (c0 < vl) ? s[nb][2] * 0.125f : -1e30f;
            s[nb][3] = (c1 < vl) ? s[nb][3] * 0.125f : -1e30f;
        }

        float tm0 = -1e30f, tm1 = -1e30f;
        #pragma unroll
        for (int nb = 0; nb < 8; nb++) {
            tm0 = fmaxf(tm0, fmaxf(s[nb][0], s[nb][1]));
            tm1 = fmaxf(tm1, fmaxf(s[nb][2], s[nb][3]));
        }
        tm0 = fmaxf(tm0, __shfl_xor_sync(0xffffffffu, tm0, 1));
        tm0 = fmaxf(tm0, __shfl_xor_sync(0xffffffffu, tm0, 2));
        tm1 = fmaxf(tm1, __shfl_xor_sync(0xffffffffu, tm1, 1));
        tm1 = fmaxf(tm1, __shfl_xor_sync(0xffffffffu, tm1, 2));

        float mn0 = fmaxf(m0, tm0);
        float mn1 = fmaxf(m1, tm1);
        float al0 = expf_fast(m0 - mn0);
        float al1 = expf_fast(m1 - mn1);

        uint32_t pAh[4][4], pAl[4][4];
        float ls0 = 0.f, ls1 = 0.f;
        #pragma unroll
        for (int nb = 0; nb < 8; nb++) {
            float p0 = expf_fast(s[nb][0] - mn0);
            float p1 = expf_fast(s[nb][1] - mn0);
            float p2 = expf_fast(s[nb][2] - mn1);
            float p3 = expf_fast(s[nb][3] - mn1);
            ls0 += p0 + p1;
            ls1 += p2 + p3;
            float h0 = __half2float(__float2half_rn(p0));
            float h1 = __half2float(__float2half_rn(p1));
            float h2 = __half2float(__float2half_rn(p2));
            float h3 = __half2float(__float2half_rn(p3));
            int ks = nb >> 1;
            int hf = (nb & 1) * 2;
            pAh[ks][hf + 0] = pack_h2(h0, h1);
            pAh[ks][hf + 1] = pack_h2(h2, h3);
            pAl[ks][hf + 0] = pack_h2(p0 - h0, p1 - h1);
            pAl[ks][hf + 1] = pack_h2(p2 - h2, p3 - h3);
        }
        ls0 += __shfl_xor_sync(0xffffffffu, ls0, 1);
        ls0 += __shfl_xor_sync(0xffffffffu, ls0, 2);
        ls1 += __shfl_xor_sync(0xffffffffu, ls1, 1);
        ls1 += __shfl_xor_sync(0xffffffffu, ls1, 2);

        l0 = l0 * al0 + ls0;
        l1 = l1 * al1 + ls1;
        m0 = mn0;
        m1 = mn1;

        #pragma unroll
        for (int nb = 0; nb < 8; nb++) {
            o[nb][0] *= al0; o[nb][1] *= al0;
            o[nb][2] *= al1; o[nb][3] *= al1;
        }

        // O += (Ph+Pl) V
        #pragma unroll
        for (int kk = 0; kk < 4; kk++) {
            uint32_t a0h = pAh[kk][0], a1h = pAh[kk][1], a2h = pAh[kk][2], a3h = pAh[kk][3];
            uint32_t a0l = pAl[kk][0], a1l = pAl[kk][1], a2l = pAl[kk][2], a3l = pAl[kk][3];
            #pragma unroll
            for (int nb = 0; nb < 4; nb++) {
                int r = kk * 16 + (lane & 15);
                int c = nb * 16 + (lane >> 4) * 8;
                uint32_t va = cur + 9216 + r * 144 + c * 2;
                uint32_t vh0, vh1, vh2, vh3;
                LDSM_X4_T(vh0, vh1, vh2, vh3, va);
                MMAH(o[2*nb],   a0h, a1h, a2h, a3h, vh0, vh1);
                MMAH(o[2*nb],   a0l, a1l, a2l, a3l, vh0, vh1);
                MMAH(o[2*nb+1], a0h, a1h, a2h, a3h, vh2, vh3);
                MMAH(o[2*nb+1], a0l, a1l, a2l, a3l, vh2, vh3);
            }
        }
    }

    float inv0 = 1.f / l0;
    float inv1 = 1.f / l1;
    int row0g = q0 + warp * 16 + g;
    int row1g = row0g + 8;
    __half* Ohb = Oh + base;
    __half* Olb = Ol + base;
    #pragma unroll
    for (int nb = 0; nb < 8; nb++) {
        int col = nb * 8 + 2 * t;
        float v0 = o[nb][0] * inv0, v1 = o[nb][1] * inv0;
        float v2 = o[nb][2] * inv1, v3 = o[nb][3] * inv1;
        float h0 = __half2float(__float2half_rn(v0));
        float h1 = __half2float(__float2half_rn(v1));
        float h2 = __half2float(__float2half_rn(v2));
        float h3 = __half2float(__float2half_rn(v3));
        *(uint32_t*)(Ohb + (size_t)row0g * DD + col) = pack_h2(h0, h1);
        *(uint32_t*)(Ohb + (size_t)row1g * DD + col) = pack_h2(h2, h3);
        *(uint32_t*)(Olb + (size_t)row0g * DD + col) = pack_h2(v0 - h0, v1 - h1);
        *(uint32_t*)(Olb + (size_t)row1g * DD + col) = pack_h2(v2 - h2, v3 - h3);
    }
}

// ---------------- fused residual + LayerNorm --------------------------------
template<int SPLIT>
__global__ __launch_bounds__(256)
void ln_kernel(const float* __restrict__ A,
               const float* __restrict__ R,
               const float* __restrict__ g,
               const float* __restrict__ be,
               float* __restrict__ out,
               __half* __restrict__ oh,
               __half* __restrict__ ol)
{
    int row = blockIdx.x;
    int t   = threadIdx.x;
    const float4* a4 = (const float4*)(A + (size_t)row * DD);
    const float4* r4 = (const float4*)(R + (size_t)row * DD);
    float4 av = a4[t];
    float4 rv = r4[t];
    float x0 = av.x + rv.x, x1 = av.y + rv.y, x2 = av.z + rv.z, x3 = av.w + rv.w;

    float s = x0 + x1 + x2 + x3;
    float q = x0 * x0 + x1 * x1 + x2 * x2 + x3 * x3;
    #pragma unroll
    for (int off = 16; off >= 1; off >>= 1) {
        s += __shfl_xor_sync(0xffffffffu, s, off);
        q += __shfl_xor_sync(0xffffffffu, q, off);
    }
    __shared__ float rs[8], rq[8];
    int w = t >> 5, lane = t & 31;
    if (lane == 0) { rs[w] = s; rq[w] = q; }
    __syncthreads();
    float tot = 0.f, totq = 0.f;
    #pragma unroll
    for (int i = 0; i < 8; i++) { tot += rs[i]; totq += rq[i]; }

    float mean = tot * (1.f / DD);
    float var  = totq * (1.f / DD) - mean * mean;
    float rstd = rsqrtf(var + EPSL);

    float4 gv = ((const float4*)g)[t];
    float4 bv = ((const float4*)be)[t];
    float4 ov;
    ov.x = (x0 - mean) * rstd * gv.x + bv.x;
    ov.y = (x1 - mean) * rstd * gv.y + bv.y;
    ov.z = (x2 - mean) * rstd * gv.z + bv.z;
    ov.w = (x3 - mean) * rstd * gv.w + bv.w;
    ((float4*)(out + (size_t)row * DD))[t] = ov;

    if (SPLIT) {
        float a[4] = {ov.x, ov.y, ov.z, ov.w};
        uint2 uh, ul;
        __half* hp = (__half*)&uh;
        __half* lp = (__half*)&ul;
        #pragma unroll
        for (int j = 0; j < 4; j++) {
            __half h = __float2half_rn(a[j]);
            hp[j] = h;
            lp[j] = __float2half_rn(a[j] - __half2float(h));
        }
        ((uint2*)(oh + (size_t)row * DD))[t] = uh;
        ((uint2*)(ol + (size_t)row * DD))[t] = ul;
    }
}

// ---------------- launch ----------------------------------------------------
extern "C" void kernel_launch(void* const* d_in, const int* in_sizes, int n_in,
                              void* d_out, int out_size)
{
    const float* x   = (const float*)d_in[0];
    const int*   vl  = (const int*)  d_in[1];
    const float* Wq  = (const float*)d_in[2];
    const float* Wk  = (const float*)d_in[3];
    const float* Wv  = (const float*)d_in[4];
    const float* Wo  = (const float*)d_in[5];
    const float* W1  = (const float*)d_in[6];
    const float* b1  = (const float*)d_in[7];
    const float* W2  = (const float*)d_in[8];
    const float* b2  = (const float*)d_in[9];
    const float* g1  = (const float*)d_in[10];
    const float* be1 = (const float*)d_in[11];
    const float* g2  = (const float*)d_in[12];
    const float* be2 = (const float*)d_in[13];
    float* out = (float*)d_out;

    float *q, *k, *r;
    cudaGetSymbolAddress((void**)&q, g_q);
    cudaGetSymbolAddress((void**)&k, g_k);
    cudaGetSymbolAddress((void**)&r, g_r);

    __half *xh,*xl,*qh,*ql,*kvh,*vvh,*ah,*al,*rh,*rl,*ffh,*ffl;
    cudaGetSymbolAddress((void**)&xh, g_xh);   cudaGetSymbolAddress((void**)&xl, g_xl);
    cudaGetSymbolAddress((void**)&qh, g_qh);   cudaGetSymbolAddress((void**)&ql, g_ql);
    cudaGetSymbolAddress((void**)&kvh, g_kvh); cudaGetSymbolAddress((void**)&vvh, g_vvh);
    cudaGetSymbolAddress((void**)&ah, g_ah);   cudaGetSymbolAddress((void**)&al, g_al);
    cudaGetSymbolAddress((void**)&rh, g_rh);   cudaGetSymbolAddress((void**)&rl, g_rl);
    cudaGetSymbolAddress((void**)&ffh, g_ffh); cudaGetSymbolAddress((void**)&ffl, g_ffl);

    __half *wqkv, *wo, *w1, *w2;
    cudaGetSymbolAddress((void**)&wqkv, g_wqkv);
    cudaGetSymbolAddress((void**)&wo, g_wo);
    cudaGetSymbolAddress((void**)&w1, g_w1);
    cudaGetSymbolAddress((void**)&w2, g_w2);

    int gemm_smem = NST * STG3;   // 87552
    cudaFuncSetAttribute(hgemm3_kernel<0>, cudaFuncAttributeMaxDynamicSharedMemorySize, gemm_smem);
    cudaFuncSetAttribute(hgemm3_kernel<1>, cudaFuncAttributeMaxDynamicSharedMemorySize, gemm_smem);
    cudaFuncSetAttribute(hgemm3_kernel<2>, cudaFuncAttributeMaxDynamicSharedMemorySize, gemm_smem);
    cudaFuncSetAttribute(hgemm3_kernel<3>, cudaFuncAttributeMaxDynamicSharedMemorySize, gemm_smem);

    // one-shot split/convert of all tensors
    SplitArgs sa;
    sa.s[0] = {Wq, wqkv,        nullptr, DD*DD/1024, DD, 3*DD, 0};
    sa.s[1] = {Wk, wqkv,        nullptr, DD*DD/1024, DD, 3*DD, DD};
    sa.s[2] = {Wv, wqkv,        nullptr, DD*DD/1024, DD, 3*DD, 2*DD};
    sa.s[3] = {Wo, wo,          nullptr, DD*DD/1024, DD, DD,  0};
    sa.s[4] = {W1, w1,          nullptr, DD*FF/1024, FF, FF,  0};
    sa.s[5] = {W2, w2,          nullptr, DD*FF/1024, DD, DD,  0};
    sa.s[6] = {x,  xh,          xl,      NR*DD/1024, DD, DD,  0};
    int nblk = 0;
    for (int i = 0; i < 7; i++) nblk += sa.s[i].nblk;
    split_all_kernel<<<nblk, 256>>>(sa);

    dim3 gQKV(3 * DD / 128, NR / 128);   // (24, 64)
    dim3 gD(DD / 128, NR / 128);         // (8, 64)
    dim3 gF(FF / 128, NR / 128);         // (32, 64)

    // fused QKV projection: emits Qh/Ql split + Kh + Vh fp16
    hgemm3_kernel<3><<<gQKV, 256, gemm_smem>>>(NR, 3 * DD, DD, xh, xl, wqkv,
                                               nullptr, nullptr, qh, ql, kvh, vvh);

    // attention -> split output
    attn_f16_kernel<<<dim3(SS / 64, BB * HH), 128>>>(qh, ql, kvh, vvh, vl, ah, al);

    // output projection -> q fp32
    hgemm3_kernel<0><<<gD, 256, gemm_smem>>>(NR, DD, DD, ah, al, wo,
                                             nullptr, q, nullptr, nullptr, nullptr, nullptr);

    // residual + LN1 -> r fp32 + split
    ln_kernel<1><<<NR, 256>>>(q, x, g1, be1, r, rh, rl);

    // FFN
    hgemm3_kernel<1><<<gF, 256, gemm_smem>>>(NR, FF, DD, rh, rl, w1,
                                             b1, nullptr, ffh, ffl, nullptr, nullptr);
    hgemm3_kernel<2><<<gD, 256, gemm_smem>>>(NR, DD, FF, ffh, ffl, w2,
                                             b2, k, nullptr, nullptr, nullptr, nullptr);

    // residual + LN2 -> output
    ln_kernel<0><<<NR, 256>>>(k, r, g2, be2, out, nullptr, nullptr);
}

// round 8
// speedup vs baseline: 4.0852x; 1.0412x over previous
#include <cuda_runtime.h>
#include <cuda_fp16.h>
#include <math.h>
#include <stdint.h>

// Problem constants
#define BB   4
#define SS   2048
#define DD   1024
#define HH   16
#define HD   64
#define FF   4096
#define NR   (BB*SS)          // 8192 rows
#define EPSL 1e-5f

// ---------------- scratch (device globals; no allocation allowed) ----------
__device__ float g_q [NR*DD];        // Wo output
__device__ float g_k [NR*DD];        // FF2 output
__device__ float g_r [NR*DD];        // LN1 output fp32

// fp16 activations
__device__ __align__(16) __half g_xh [NR*DD], g_xl [NR*DD];
__device__ __align__(16) __half g_qh [NR*DD], g_ql [NR*DD];
__device__ __align__(16) __half g_kvh[NR*DD], g_vvh[NR*DD];
__device__ __align__(16) __half g_ah [NR*DD], g_al [NR*DD];
__device__ __align__(16) __half g_rh [NR*DD], g_rl [NR*DD];
__device__ __align__(16) __half g_ffh[(size_t)NR*FF], g_ffl[(size_t)NR*FF];

// fp16 weights (hi only). QKV concatenated along N: [DD, 3*DD]
__device__ __align__(16) __half g_wqkv[DD*3*DD];
__device__ __align__(16) __half g_wo  [DD*DD];
__device__ __align__(16) __half g_w1  [(size_t)DD*FF];
__device__ __align__(16) __half g_w2  [(size_t)DD*FF];

// ---------------- asm helpers ------------------------------------------------
#define LDSM_X4(R0,R1,R2,R3,ADDR) \
    asm volatile("ldmatrix.sync.aligned.m8n8.x4.shared.b16 {%0,%1,%2,%3},[%4];" \
        : "=r"(R0),"=r"(R1),"=r"(R2),"=r"(R3) : "r"(ADDR))

#define LDSM_X4_T(R0,R1,R2,R3,ADDR) \
    asm volatile("ldmatrix.sync.aligned.m8n8.x4.trans.shared.b16 {%0,%1,%2,%3},[%4];" \
        : "=r"(R0),"=r"(R1),"=r"(R2),"=r"(R3) : "r"(ADDR))

#define MMAH(D,A0,A1,A2,A3,B0,B1) \
    asm volatile("mma.sync.aligned.m16n8k16.row.col.f32.f16.f16.f32 " \
        "{%0,%1,%2,%3},{%4,%5,%6,%7},{%8,%9},{%0,%1,%2,%3};" \
        : "+f"(D[0]),"+f"(D[1]),"+f"(D[2]),"+f"(D[3]) \
        : "r"(A0),"r"(A1),"r"(A2),"r"(A3),"r"(B0),"r"(B1))

__device__ __forceinline__ void cp16(uint32_t dst, const void* src) {
    asm volatile("cp.async.cg.shared.global [%0],[%1],16;" :: "r"(dst), "l"(src));
}
#define CP_COMMIT() asm volatile("cp.async.commit_group;" ::: "memory")
#define CP_WAIT0()  asm volatile("cp.async.wait_group 0;" ::: "memory")
#define CP_WAIT1()  asm volatile("cp.async.wait_group 1;" ::: "memory")

__device__ __forceinline__ uint32_t pack_h2(float a, float b) {
    __half2 h = __floats2half2_rn(a, b);
    return *reinterpret_cast<uint32_t*>(&h);
}

// fast exp on the FMA pipe. x <= 0 expected. ~2e-6 rel err.
__device__ __forceinline__ float expf_fast(float x) {
    float y = fmaxf(x * 1.44269504088896f, -126.f);
    float fl = floorf(y);
    float f = y - fl;
    float p = 1.54653240e-4f;
    p = fmaf(p, f, 1.33335581e-3f);
    p = fmaf(p, f, 9.61812910e-3f);
    p = fmaf(p, f, 5.55041086e-2f);
    p = fmaf(p, f, 2.40226507e-1f);
    p = fmaf(p, f, 6.93147181e-1f);
    p = fmaf(p, f, 1.0f);
    int ei = (int)fl;
    float sc = __int_as_float((ei + 127) << 23);
    return p * sc;
}

// ---------------- one-shot fp32 -> fp16 (hi[,lo]) split, all tensors ---------
struct SplitSeg {
    const float* src;
    __half* h;
    __half* l;        // nullptr -> hi only
    int nblk;         // blocks of 1024 elems
    int cols;         // source row length
    int stride;       // dst row stride
    int off;          // dst column offset
};
struct SplitArgs { SplitSeg s[7]; };

__global__ __launch_bounds__(256)
void split_all_kernel(SplitArgs a)
{
    int blk = blockIdx.x;
    int i = 0;
    while (blk >= a.s[i].nblk) { blk -= a.s[i].nblk; i++; }
    SplitSeg sg = a.s[i];

    int e   = blk * 1024 + threadIdx.x * 4;
    int row = e / sg.cols;
    int col = e - row * sg.cols;
    size_t d = (size_t)row * sg.stride + sg.off + col;

    float4 v = *(const float4*)(sg.src + (size_t)e);
    float av[4] = {v.x, v.y, v.z, v.w};
    uint2 uh, ul;
    __half* hp = (__half*)&uh;
    __half* lp = (__half*)&ul;
    #pragma unroll
    for (int j = 0; j < 4; j++) {
        __half h = __float2half_rn(av[j]);
        hp[j] = h;
        lp[j] = __float2half_rn(av[j] - __half2float(h));
    }
    *(uint2*)(sg.h + d) = uh;
    if (sg.l) *(uint2*)(sg.l + d) = ul;
}

// ---------------- HMMA GEMM, 2-term fp16 split, 2-stage, 2 CTAs/SM -----------
// C[M,N] = (Ah+Al)[M,K] @ Bh[K,N]
// BM=BN=128, BK=32, 256 threads (8 warps 2x4), warp tile 64x32.
// stage: Ah 10240 + Al 10240 + Bh 8704 = 29184 B, 2 stages = 58368 B
// -> two CTAs co-resident per SM to fill the tensor pipe.
#define PAB 80
#define PBB 272
#define STG3 29184
#define NST 2

__device__ __forceinline__ void load_stage3(
    uint32_t sb,
    const __half* __restrict__ Ah, const __half* __restrict__ Al,
    const __half* __restrict__ Bh, int K, int N, int tid)
{
    #pragma unroll
    for (int it = 0; it < 2; it++) {
        int idx = it * 256 + tid;
        int r = idx >> 2, c4 = idx & 3;
        uint32_t d = sb + r * PAB + c4 * 16;
        size_t so = (size_t)r * K + c4 * 8;
        cp16(d,         Ah + so);
        cp16(d + 10240, Al + so);
    }
    #pragma unroll
    for (int it = 0; it < 2; it++) {
        int idx = it * 256 + tid;
        int r = idx >> 4, c16 = idx & 15;
        cp16(sb + 20480 + r * PBB + c16 * 16, Bh + (size_t)r * N + c16 * 8);
    }
}

// EPI: 0 plain fp32 | 1 bias+relu -> split fp16 | 2 bias -> fp32 | 3 QKV fused
template<int EPI>
__global__ __launch_bounds__(256, 2)
void hgemm3_kernel(int M, int N, int K,
                   const __half* __restrict__ Ah,
                   const __half* __restrict__ Al,
                   const __half* __restrict__ Bh,
                   const float* __restrict__ bias,
                   float* __restrict__ C,
                   __half* __restrict__ Ch,
                   __half* __restrict__ Cl,
                   __half* __restrict__ Ko,
                   __half* __restrict__ Vo)
{
    extern __shared__ __align__(16) char smem[];
    uint32_t sb = (uint32_t)__cvta_generic_to_shared(smem);

    int tid  = threadIdx.x;
    int lane = tid & 31;
    int warp = tid >> 5;
    int wm = warp & 1;
    int wn = warp >> 1;
    int row0 = blockIdx.y * 128;
    int col0 = blockIdx.x * 128;

    const __half* Ahb = Ah + (size_t)row0 * K;
    const __half* Alb = Al + (size_t)row0 * K;
    const __half* Bhb = Bh + col0;

    float acc[4][4][4];
    #pragma unroll
    for (int i = 0; i < 4; i++)
        #pragma unroll
        for (int j = 0; j < 4; j++)
            #pragma unroll
            for (int c = 0; c < 4; c++) acc[i][j][c] = 0.f;

    int NT = K / 32;

    // prologue: stage 0
    load_stage3(sb, Ahb, Alb, Bhb, K, N, tid);
    CP_COMMIT();

    for (int kt = 0; kt < NT; kt++) {
        CP_WAIT0();
        __syncthreads();

        int nk = kt + 1;
        if (nk < NT) {
            load_stage3(sb + (nk & 1) * STG3, Ahb + nk * 32, Alb + nk * 32,
                        Bhb + (size_t)(nk * 32) * N, K, N, tid);
            CP_COMMIT();
        }

        uint32_t st = sb + (kt & 1) * STG3;
        #pragma unroll
        for (int kk = 0; kk < 32; kk += 16) {
            uint32_t ahi[4][4], alo[4][4], bfr[4][2];

            #pragma unroll
            for (int mi = 0; mi < 4; mi++) {
                int r = wm * 64 + mi * 16 + (lane & 15);
                int c = kk + (lane >> 4) * 8;
                uint32_t ah = st + r * PAB + c * 2;
                LDSM_X4(ahi[mi][0], ahi[mi][1], ahi[mi][2], ahi[mi][3], ah);
                LDSM_X4(alo[mi][0], alo[mi][1], alo[mi][2], alo[mi][3], ah + 10240);
            }
            #pragma unroll
            for (int nb2 = 0; nb2 < 2; nb2++) {
                int r = kk + (lane & 15);
                int c = wn * 32 + nb2 * 16 + (lane >> 4) * 8;
                uint32_t bh = st + 20480 + r * PBB + c * 2;
                LDSM_X4_T(bfr[nb2*2][0], bfr[nb2*2][1], bfr[nb2*2+1][0], bfr[nb2*2+1][1], bh);
            }

            #pragma unroll
            for (int mi = 0; mi < 4; mi++)
                #pragma unroll
                for (int ni = 0; ni < 4; ni++) {
                    MMAH(acc[mi][ni], ahi[mi][0], ahi[mi][1], ahi[mi][2], ahi[mi][3],
                         bfr[ni][0], bfr[ni][1]);
                    MMAH(acc[mi][ni], alo[mi][0], alo[mi][1], alo[mi][2], alo[mi][3],
                         bfr[ni][0], bfr[ni][1]);
                }
        }
    }

    // epilogue
    int g = lane >> 2, t = lane & 3;
    int region = col0 >> 10;         // EPI 3 only
    int lc0 = col0 & 1023;
    #pragma unroll
    for (int mi = 0; mi < 4; mi++) {
        #pragma unroll
        for (int ni = 0; ni < 4; ni++) {
            int r = row0 + wm * 64 + mi * 16 + g;
            int cc = wn * 32 + ni * 8 + t * 2;
            float v0 = acc[mi][ni][0], v1 = acc[mi][ni][1];
            float v2 = acc[mi][ni][2], v3 = acc[mi][ni][3];

            if (EPI == 1 || EPI == 2) {
                int c = col0 + cc;
                float bz0 = bias[c], bz1 = bias[c + 1];
                v0 += bz0; v1 += bz1; v2 += bz0; v3 += bz1;
            }
            if (EPI == 1) {
                v0 = fmaxf(v0, 0.f); v1 = fmaxf(v1, 0.f);
                v2 = fmaxf(v2, 0.f); v3 = fmaxf(v3, 0.f);
            }

            if (EPI == 0 || EPI == 2) {
                int c = col0 + cc;
                *(float2*)&C[(size_t)r * N + c]       = make_float2(v0, v1);
                *(float2*)&C[(size_t)(r + 8) * N + c] = make_float2(v2, v3);
            } else if (EPI == 1) {
                int c = col0 + cc;
                float h0 = __half2float(__float2half_rn(v0));
                float h1 = __half2float(__float2half_rn(v1));
                float h2 = __half2float(__float2half_rn(v2));
                float h3 = __half2float(__float2half_rn(v3));
                *(uint32_t*)&Ch[(size_t)r * N + c]       = pack_h2(h0, h1);
                *(uint32_t*)&Ch[(size_t)(r + 8) * N + c] = pack_h2(h2, h3);
                *(uint32_t*)&Cl[(size_t)r * N + c]       = pack_h2(v0 - h0, v1 - h1);
                *(uint32_t*)&Cl[(size_t)(r + 8) * N + c] = pack_h2(v2 - h2, v3 - h3);
            } else {   // EPI == 3
                int lc = lc0 + cc;
                if (region == 0) {
                    float h0 = __half2float(__float2half_rn(v0));
                    float h1 = __half2float(__float2half_rn(v1));
                    float h2 = __half2float(__float2half_rn(v2));
                    float h3 = __half2float(__float2half_rn(v3));
                    *(uint32_t*)&Ch[(size_t)r * DD + lc]       = pack_h2(h0, h1);
                    *(uint32_t*)&Ch[(size_t)(r + 8) * DD + lc] = pack_h2(h2, h3);
                    *(uint32_t*)&Cl[(size_t)r * DD + lc]       = pack_h2(v0 - h0, v1 - h1);
                    *(uint32_t*)&Cl[(size_t)(r + 8) * DD + lc] = pack_h2(v2 - h2, v3 - h3);
                } else {
                    __half* KV = (region == 1) ? Ko : Vo;
                    *(uint32_t*)&KV[(size_t)r * DD + lc]       = pack_h2(v0, v1);
                    *(uint32_t*)&KV[(size_t)(r + 8) * DD + lc] = pack_h2(v2, v3);
                }
            }
        }
    }
}

// ---------------- flash attention: pre-split fp16, cp.async, 2-term ----------
// smem: two 18432B KV buffers (K at +0, V at +9216), pitch 144B.
__device__ __forceinline__ void load_kv(uint32_t buf,
                                        const __half* __restrict__ KhB,
                                        const __half* __restrict__ VhB,
                                        int k0, int tid)
{
    #pragma unroll
    for (int it = 0; it < 4; it++) {
        int idx = it * 128 + tid;
        int r = idx >> 3, c = idx & 7;
        cp16(buf + r * 144 + c * 16,        KhB + (size_t)(k0 + r) * DD + c * 8);
        cp16(buf + 9216 + r * 144 + c * 16, VhB + (size_t)(k0 + r) * DD + c * 8);
    }
}

__global__ __launch_bounds__(128)
void attn_f16_kernel(const __half* __restrict__ Qh, const __half* __restrict__ Ql,
                     const __half* __restrict__ Kh, const __half* __restrict__ Vh,
                     const int* __restrict__ vlen,
                     __half* __restrict__ Oh, __half* __restrict__ Ol)
{
    __shared__ __align__(16) char smem[36864];
    uint32_t sb = (uint32_t)__cvta_generic_to_shared(smem);

    int tid  = threadIdx.x;
    int lane = tid & 31;
    int warp = tid >> 5;
    int g    = lane >> 2;
    int t    = lane & 3;

    int bh = blockIdx.y;
    int b  = bh >> 4;
    int h  = bh & 15;
    int q0 = blockIdx.x * 64;
    int vl = vlen[b];

    size_t base = (size_t)(b * SS) * DD + h * HD;
    const __half* QhB = Qh + base + (size_t)q0 * DD;
    const __half* QlB = Ql + base + (size_t)q0 * DD;
    const __half* KhB = Kh + base;
    const __half* VhB = Vh + base;

    // stage Q (hi at sb, lo at sb+9216)
    #pragma unroll
    for (int it = 0; it < 4; it++) {
        int idx = it * 128 + tid;
        int r = idx >> 3, c = idx & 7;
        cp16(sb + r * 144 + c * 16,        QhB + (size_t)r * DD + c * 8);
        cp16(sb + 9216 + r * 144 + c * 16, QlB + (size_t)r * DD + c * 8);
    }
    CP_COMMIT(); CP_WAIT0();
    __syncthreads();

    uint32_t qh[4][4], ql[4][4];
    #pragma unroll
    for (int kk = 0; kk < 4; kk++) {
        int r = warp * 16 + (lane & 15);
        int c = kk * 16 + (lane >> 4) * 8;
        LDSM_X4(qh[kk][0], qh[kk][1], qh[kk][2], qh[kk][3], sb + r * 144 + c * 2);
        LDSM_X4(ql[kk][0], ql[kk][1], ql[kk][2], ql[kk][3], sb + 9216 + r * 144 + c * 2);
    }
    __syncthreads();    // Q frags read; buffer 0 reusable

    float o[8][4];
    #pragma unroll
    for (int i = 0; i < 8; i++)
        #pragma unroll
        for (int c = 0; c < 4; c++) o[i][c] = 0.f;
    float m0 = -1e30f, m1 = -1e30f, l0 = 0.f, l1 = 0.f;

    int nkt = (vl + 63) >> 6;

    load_kv(sb, KhB, VhB, 0, tid);
    CP_COMMIT();

    for (int kt = 0; kt < nkt; kt++) {
        __syncthreads();     // compute of kt-1 done before overwriting its buffer
        if (kt + 1 < nkt)
            load_kv(sb + ((kt + 1) & 1) * 18432, KhB, VhB, (kt + 1) * 64, tid);
        CP_COMMIT();
        CP_WAIT1();
        __syncthreads();     // tile kt resident for all warps

        uint32_t cur = sb + (kt & 1) * 18432;
        int k0 = kt * 64;

        // S = (Qh+Ql) Kh^T
        float s[8][4];
        #pragma unroll
        for (int i = 0; i < 8; i++)
            #pragma unroll
            for (int c = 0; c < 4; c++) s[i][c] = 0.f;

        #pragma unroll
        for (int kk = 0; kk < 4; kk++) {
            #pragma unroll
            for (int nb = 0; nb < 4; nb++) {
                int r = nb * 16 + (lane & 15);
                int c = kk * 16 + (lane >> 4) * 8;
                uint32_t ka = cur + r * 144 + c * 2;
                uint32_t kh0, kh1, kh2, kh3;
                LDSM_X4(kh0, kh1, kh2, kh3, ka);
                MMAH(s[2*nb],   qh[kk][0], qh[kk][1], qh[kk][2], qh[kk][3], kh0, kh2);
                MMAH(s[2*nb],   ql[kk][0], ql[kk][1], ql[kk][2], ql[kk][3], kh0, kh2);
                MMAH(s[2*nb+1], qh[kk][0], qh[kk][1], qh[kk][2], qh[kk][3], kh1, kh3);
                MMAH(s[2*nb+1], ql[kk][0], ql[kk][1], ql[kk][2], ql[kk][3], kh1, kh3);
            }
        }

        // scale + mask
        #pragma unroll
        for (int nb = 0; nb < 8; nb++) {
            int c0 = k0 + nb * 8 + 2 * t;
            int c1 = c0 + 1;
            s[nb][0] = (c0 < vl) ? s[nb][0] * 0.125f : -1e30f;
            s[nb][1] = (c1 < vl) ? s[nb][1] * 0.125f : -1e30f;
            s[nb][2] = (c0 < vl) ? s[nb][2] * 0.125f : -1e30f;
            s[nb][3] = (c1 < vl) ? s[nb][3] * 0.125f : -1e30f;
        }

        float tm0 = -1e30f, tm1 = -1e30f;
        #pragma unroll
        for (int nb = 0; nb < 8; nb++) {
            tm0 = fmaxf(tm0, fmaxf(s[nb][0], s[nb][1]));
            tm1 = fmaxf(tm1, fmaxf(s[nb][2], s[nb][3]));
        }
        tm0 = fmaxf(tm0, __shfl_xor_sync(0xffffffffu, tm0, 1));
        tm0 = fmaxf(tm0, __shfl_xor_sync(0xffffffffu, tm0, 2));
        tm1 = fmaxf(tm1, __shfl_xor_sync(0xffffffffu, tm1, 1));
        tm1 = fmaxf(tm1, __shfl_xor_sync(0xffffffffu, tm1, 2));

        float mn0 = fmaxf(m0, tm0);
        float mn1 = fmaxf(m1, tm1);
        float al0 = expf_fast(m0 - mn0);
        float al1 = expf_fast(m1 - mn1);

        uint32_t pAh[4][4], pAl[4][4];
        float ls0 = 0.f, ls1 = 0.f;
        #pragma unroll
        for (int nb = 0; nb < 8; nb++) {
            float p0 = expf_fast(s[nb][0] - mn0);
            float p1 = expf_fast(s[nb][1] - mn0);
            float p2 = expf_fast(s[nb][2] - mn1);
            float p3 = expf_fast(s[nb][3] - mn1);
            ls0 += p0 + p1;
            ls1 += p2 + p3;
            float h0 = __half2float(__float2half_rn(p0));
            float h1 = __half2float(__float2half_rn(p1));
            float h2 = __half2float(__float2half_rn(p2));
            float h3 = __half2float(__float2half_rn(p3));
            int ks = nb >> 1;
            int hf = (nb & 1) * 2;
            pAh[ks][hf + 0] = pack_h2(h0, h1);
            pAh[ks][hf + 1] = pack_h2(h2, h3);
            pAl[ks][hf + 0] = pack_h2(p0 - h0, p1 - h1);
            pAl[ks][hf + 1] = pack_h2(p2 - h2, p3 - h3);
        }
        ls0 += __shfl_xor_sync(0xffffffffu, ls0, 1);
        ls0 += __shfl_xor_sync(0xffffffffu, ls0, 2);
        ls1 += __shfl_xor_sync(0xffffffffu, ls1, 1);
        ls1 += __shfl_xor_sync(0xffffffffu, ls1, 2);

        l0 = l0 * al0 + ls0;
        l1 = l1 * al1 + ls1;
        m0 = mn0;
        m1 = mn1;

        #pragma unroll
        for (int nb = 0; nb < 8; nb++) {
            o[nb][0] *= al0; o[nb][1] *= al0;
            o[nb][2] *= al1; o[nb][3] *= al1;
        }

        // O += (Ph+Pl) V
        #pragma unroll
        for (int kk = 0; kk < 4; kk++) {
            uint32_t a0h = pAh[kk][0], a1h = pAh[kk][1], a2h = pAh[kk][2], a3h = pAh[kk][3];
            uint32_t a0l = pAl[kk][0], a1l = pAl[kk][1], a2l = pAl[kk][2], a3l = pAl[kk][3];
            #pragma unroll
            for (int nb = 0; nb < 4; nb++) {
                int r = kk * 16 + (lane & 15);
                int c = nb * 16 + (lane >> 4) * 8;
                uint32_t va = cur + 9216 + r * 144 + c * 2;
                uint32_t vh0, vh1, vh2, vh3;
                LDSM_X4_T(vh0, vh1, vh2, vh3, va);
                MMAH(o[2*nb],   a0h, a1h, a2h, a3h, vh0, vh1);
                MMAH(o[2*nb],   a0l, a1l, a2l, a3l, vh0, vh1);
                MMAH(o[2*nb+1], a0h, a1h, a2h, a3h, vh2, vh3);
                MMAH(o[2*nb+1], a0l, a1l, a2l, a3l, vh2, vh3);
            }
        }
    }

    float inv0 = 1.f / l0;
    float inv1 = 1.f / l1;
    int row0g = q0 + warp * 16 + g;
    int row1g = row0g + 8;
    __half* Ohb = Oh + base;
    __half* Olb = Ol + base;
    #pragma unroll
    for (int nb = 0; nb < 8; nb++) {
        int col = nb * 8 + 2 * t;
        float v0 = o[nb][0] * inv0, v1 = o[nb][1] * inv0;
        float v2 = o[nb][2] * inv1, v3 = o[nb][3] * inv1;
        float h0 = __half2float(__float2half_rn(v0));
        float h1 = __half2float(__float2half_rn(v1));
        float h2 = __half2float(__float2half_rn(v2));
        float h3 = __half2float(__float2half_rn(v3));
        *(uint32_t*)(Ohb + (size_t)row0g * DD + col) = pack_h2(h0, h1);
        *(uint32_t*)(Ohb + (size_t)row1g * DD + col) = pack_h2(h2, h3);
        *(uint32_t*)(Olb + (size_t)row0g * DD + col) = pack_h2(v0 - h0, v1 - h1);
        *(uint32_t*)(Olb + (size_t)row1g * DD + col) = pack_h2(v2 - h2, v3 - h3);
    }
}

// ---------------- fused residual + LayerNorm --------------------------------
template<int SPLIT>
__global__ __launch_bounds__(256)
void ln_kernel(const float* __restrict__ A,
               const float* __restrict__ R,
               const float* __restrict__ g,
               const float* __restrict__ be,
               float* __restrict__ out,
               __half* __restrict__ oh,
               __half* __restrict__ ol)
{
    int row = blockIdx.x;
    int t   = threadIdx.x;
    const float4* a4 = (const float4*)(A + (size_t)row * DD);
    const float4* r4 = (const float4*)(R + (size_t)row * DD);
    float4 av = a4[t];
    float4 rv = r4[t];
    float x0 = av.x + rv.x, x1 = av.y + rv.y, x2 = av.z + rv.z, x3 = av.w + rv.w;

    float s = x0 + x1 + x2 + x3;
    float q = x0 * x0 + x1 * x1 + x2 * x2 + x3 * x3;
    #pragma unroll
    for (int off = 16; off >= 1; off >>= 1) {
        s += __shfl_xor_sync(0xffffffffu, s, off);
        q += __shfl_xor_sync(0xffffffffu, q, off);
    }
    __shared__ float rs[8], rq[8];
    int w = t >> 5, lane = t & 31;
    if (lane == 0) { rs[w] = s; rq[w] = q; }
    __syncthreads();
    float tot = 0.f, totq = 0.f;
    #pragma unroll
    for (int i = 0; i < 8; i++) { tot += rs[i]; totq += rq[i]; }

    float mean = tot * (1.f / DD);
    float var  = totq * (1.f / DD) - mean * mean;
    float rstd = rsqrtf(var + EPSL);

    float4 gv = ((const float4*)g)[t];
    float4 bv = ((const float4*)be)[t];
    float4 ov;
    ov.x = (x0 - mean) * rstd * gv.x + bv.x;
    ov.y = (x1 - mean) * rstd * gv.y + bv.y;
    ov.z = (x2 - mean) * rstd * gv.z + bv.z;
    ov.w = (x3 - mean) * rstd * gv.w + bv.w;
    ((float4*)(out + (size_t)row * DD))[t] = ov;

    if (SPLIT) {
        float a[4] = {ov.x, ov.y, ov.z, ov.w};
        uint2 uh, ul;
        __half* hp = (__half*)&uh;
        __half* lp = (__half*)&ul;
        #pragma unroll
        for (int j = 0; j < 4; j++) {
            __half h = __float2half_rn(a[j]);
            hp[j] = h;
            lp[j] = __float2half_rn(a[j] - __half2float(h));
        }
        ((uint2*)(oh + (size_t)row * DD))[t] = uh;
        ((uint2*)(ol + (size_t)row * DD))[t] = ul;
    }
}

// ---------------- launch ----------------------------------------------------
extern "C" void kernel_launch(void* const* d_in, const int* in_sizes, int n_in,
                              void* d_out, int out_size)
{
    const float* x   = (const float*)d_in[0];
    const int*   vl  = (const int*)  d_in[1];
    const float* Wq  = (const float*)d_in[2];
    const float* Wk  = (const float*)d_in[3];
    const float* Wv  = (const float*)d_in[4];
    const float* Wo  = (const float*)d_in[5];
    const float* W1  = (const float*)d_in[6];
    const float* b1  = (const float*)d_in[7];
    const float* W2  = (const float*)d_in[8];
    const float* b2  = (const float*)d_in[9];
    const float* g1  = (const float*)d_in[10];
    const float* be1 = (const float*)d_in[11];
    const float* g2  = (const float*)d_in[12];
    const float* be2 = (const float*)d_in[13];
    float* out = (float*)d_out;

    float *q, *k, *r;
    cudaGetSymbolAddress((void**)&q, g_q);
    cudaGetSymbolAddress((void**)&k, g_k);
    cudaGetSymbolAddress((void**)&r, g_r);

    __half *xh,*xl,*qh,*ql,*kvh,*vvh,*ah,*al,*rh,*rl,*ffh,*ffl;
    cudaGetSymbolAddress((void**)&xh, g_xh);   cudaGetSymbolAddress((void**)&xl, g_xl);
    cudaGetSymbolAddress((void**)&qh, g_qh);   cudaGetSymbolAddress((void**)&ql, g_ql);
    cudaGetSymbolAddress((void**)&kvh, g_kvh); cudaGetSymbolAddress((void**)&vvh, g_vvh);
    cudaGetSymbolAddress((void**)&ah, g_ah);   cudaGetSymbolAddress((void**)&al, g_al);
    cudaGetSymbolAddress((void**)&rh, g_rh);   cudaGetSymbolAddress((void**)&rl, g_rl);
    cudaGetSymbolAddress((void**)&ffh, g_ffh); cudaGetSymbolAddress((void**)&ffl, g_ffl);

    __half *wqkv, *wo, *w1, *w2;
    cudaGetSymbolAddress((void**)&wqkv, g_wqkv);
    cudaGetSymbolAddress((void**)&wo, g_wo);
    cudaGetSymbolAddress((void**)&w1, g_w1);
    cudaGetSymbolAddress((void**)&w2, g_w2);

    int gemm_smem = NST * STG3;   // 58368
    cudaFuncSetAttribute(hgemm3_kernel<0>, cudaFuncAttributeMaxDynamicSharedMemorySize, gemm_smem);
    cudaFuncSetAttribute(hgemm3_kernel<1>, cudaFuncAttributeMaxDynamicSharedMemorySize, gemm_smem);
    cudaFuncSetAttribute(hgemm3_kernel<2>, cudaFuncAttributeMaxDynamicSharedMemorySize, gemm_smem);
    cudaFuncSetAttribute(hgemm3_kernel<3>, cudaFuncAttributeMaxDynamicSharedMemorySize, gemm_smem);

    // one-shot split/convert of all tensors
    SplitArgs sa;
    sa.s[0] = {Wq, wqkv,        nullptr, DD*DD/1024, DD, 3*DD, 0};
    sa.s[1] = {Wk, wqkv,        nullptr, DD*DD/1024, DD, 3*DD, DD};
    sa.s[2] = {Wv, wqkv,        nullptr, DD*DD/1024, DD, 3*DD, 2*DD};
    sa.s[3] = {Wo, wo,          nullptr, DD*DD/1024, DD, DD,  0};
    sa.s[4] = {W1, w1,          nullptr, DD*FF/1024, FF, FF,  0};
    sa.s[5] = {W2, w2,          nullptr, DD*FF/1024, DD, DD,  0};
    sa.s[6] = {x,  xh,          xl,      NR*DD/1024, DD, DD,  0};
    int nblk = 0;
    for (int i = 0; i < 7; i++) nblk += sa.s[i].nblk;
    split_all_kernel<<<nblk, 256>>>(sa);

    dim3 gQKV(3 * DD / 128, NR / 128);   // (24, 64)
    dim3 gD(DD / 128, NR / 128);         // (8, 64)
    dim3 gF(FF / 128, NR / 128);         // (32, 64)

    // fused QKV projection: emits Qh/Ql split + Kh + Vh fp16
    hgemm3_kernel<3><<<gQKV, 256, gemm_smem>>>(NR, 3 * DD, DD, xh, xl, wqkv,
                                               nullptr, nullptr, qh, ql, kvh, vvh);

    // attention -> split output
    attn_f16_kernel<<<dim3(SS / 64, BB * HH), 128>>>(qh, ql, kvh, vvh, vl, ah, al);

    // output projection -> q fp32
    hgemm3_kernel<0><<<gD, 256, gemm_smem>>>(NR, DD, DD, ah, al, wo,
                                             nullptr, q, nullptr, nullptr, nullptr, nullptr);

    // residual + LN1 -> r fp32 + split
    ln_kernel<1><<<NR, 256>>>(q, x, g1, be1, r, rh, rl);

    // FFN
    hgemm3_kernel<1><<<gF, 256, gemm_smem>>>(NR, FF, DD, rh, rl, w1,
                                             b1, nullptr, ffh, ffl, nullptr, nullptr);
    hgemm3_kernel<2><<<gD, 256, gemm_smem>>>(NR, DD, FF, ffh, ffl, w2,
                                             b2, k, nullptr, nullptr, nullptr, nullptr);

    // residual + LN2 -> output
    ln_kernel<0><<<NR, 256>>>(k, r, g2, be2, out, nullptr, nullptr);
}

// round 9
// speedup vs baseline: 6.8295x; 1.6718x over previous
#include <cuda_runtime.h>
#include <cuda_fp16.h>
#include <math.h>
#include <stdint.h>

// Problem constants
#define BB   4
#define SS   2048
#define DD   1024
#define HH   16
#define HD   64
#define FF   4096
#define NR   (BB*SS)          // 8192 rows
#define EPSL 1e-5f

// ---------------- scratch (device globals; no allocation allowed) ----------
__device__ float g_q [NR*DD];        // Wo output fp32
__device__ float g_k [NR*DD];        // FF2 output fp32
__device__ float g_r [NR*DD];        // LN1 output fp32

// fp16 activations (single term)
__device__ __align__(16) __half g_xh  [NR*DD];
__device__ __align__(16) __half g_qkv [(size_t)NR*3*DD];   // fused QKV output
__device__ __align__(16) __half g_ah  [NR*DD];
__device__ __align__(16) __half g_rh  [NR*DD];
__device__ __align__(16) __half g_ffh [(size_t)NR*FF];

// fp16 weights. QKV concatenated along N: [DD, 3*DD]
__device__ __align__(16) __half g_wqkv[DD*3*DD];
__device__ __align__(16) __half g_wo  [DD*DD];
__device__ __align__(16) __half g_w1  [(size_t)DD*FF];
__device__ __align__(16) __half g_w2  [(size_t)DD*FF];

// ---------------- asm helpers ------------------------------------------------
#define LDSM_X4(R0,R1,R2,R3,ADDR) \
    asm volatile("ldmatrix.sync.aligned.m8n8.x4.shared.b16 {%0,%1,%2,%3},[%4];" \
        : "=r"(R0),"=r"(R1),"=r"(R2),"=r"(R3) : "r"(ADDR))

#define LDSM_X4_T(R0,R1,R2,R3,ADDR) \
    asm volatile("ldmatrix.sync.aligned.m8n8.x4.trans.shared.b16 {%0,%1,%2,%3},[%4];" \
        : "=r"(R0),"=r"(R1),"=r"(R2),"=r"(R3) : "r"(ADDR))

#define MMAH(D,A0,A1,A2,A3,B0,B1) \
    asm volatile("mma.sync.aligned.m16n8k16.row.col.f32.f16.f16.f32 " \
        "{%0,%1,%2,%3},{%4,%5,%6,%7},{%8,%9},{%0,%1,%2,%3};" \
        : "+f"(D[0]),"+f"(D[1]),"+f"(D[2]),"+f"(D[3]) \
        : "r"(A0),"r"(A1),"r"(A2),"r"(A3),"r"(B0),"r"(B1))

__device__ __forceinline__ void cp16(uint32_t dst, const void* src) {
    asm volatile("cp.async.cg.shared.global [%0],[%1],16;" :: "r"(dst), "l"(src));
}
#define CP_COMMIT() asm volatile("cp.async.commit_group;" ::: "memory")
#define CP_WAIT0()  asm volatile("cp.async.wait_group 0;" ::: "memory")
#define CP_WAIT1()  asm volatile("cp.async.wait_group 1;" ::: "memory")

__device__ __forceinline__ uint32_t pack_h2(float a, float b) {
    __half2 h = __floats2half2_rn(a, b);
    return *reinterpret_cast<uint32_t*>(&h);
}

// fast exp on the FMA pipe. x <= 0 expected. ~2e-6 rel err.
__device__ __forceinline__ float expf_fast(float x) {
    float y = fmaxf(x * 1.44269504088896f, -126.f);
    float fl = floorf(y);
    float f = y - fl;
    float p = 1.54653240e-4f;
    p = fmaf(p, f, 1.33335581e-3f);
    p = fmaf(p, f, 9.61812910e-3f);
    p = fmaf(p, f, 5.55041086e-2f);
    p = fmaf(p, f, 2.40226507e-1f);
    p = fmaf(p, f, 6.93147181e-1f);
    p = fmaf(p, f, 1.0f);
    int ei = (int)fl;
    float sc = __int_as_float((ei + 127) << 23);
    return p * sc;
}

// ---------------- one-shot fp32 -> fp16 convert, all tensors -----------------
struct SplitSeg {
    const float* src;
    __half* h;
    int nblk;         // blocks of 1024 elems
    int cols;         // source row length
    int stride;       // dst row stride
    int off;          // dst column offset
};
struct SplitArgs { SplitSeg s[7]; };

__global__ __launch_bounds__(256)
void split_all_kernel(SplitArgs a)
{
    int blk = blockIdx.x;
    int i = 0;
    while (blk >= a.s[i].nblk) { blk -= a.s[i].nblk; i++; }
    SplitSeg sg = a.s[i];

    int e   = blk * 1024 + threadIdx.x * 4;
    int row = e / sg.cols;
    int col = e - row * sg.cols;
    size_t d = (size_t)row * sg.stride + sg.off + col;

    float4 v = *(const float4*)(sg.src + (size_t)e);
    float av[4] = {v.x, v.y, v.z, v.w};
    uint2 uh;
    __half* hp = (__half*)&uh;
    #pragma unroll
    for (int j = 0; j < 4; j++) hp[j] = __float2half_rn(av[j]);
    *(uint2*)(sg.h + d) = uh;
}

// ---------------- HMMA GEMM, single-term fp16, 3-stage, 2 CTAs/SM ------------
// C[M,N] = A[M,K] @ B[K,N], fp16 inputs, fp32 accum.
// BM=BN=128, BK=32, 256 threads (8 warps 2x4), warp tile 64x32.
// stage: A 10240 + B 8704 = 18944 B, 3 stages = 56832 B.
#define PAB 80
#define PBB 272
#define STG3 18944
#define NST 3

__device__ __forceinline__ void load_stage(
    uint32_t sb,
    const __half* __restrict__ Ah,
    const __half* __restrict__ Bh, int K, int N, int tid)
{
    #pragma unroll
    for (int it = 0; it < 2; it++) {
        int idx = it * 256 + tid;
        int r = idx >> 2, c4 = idx & 3;
        cp16(sb + r * PAB + c4 * 16, Ah + (size_t)r * K + c4 * 8);
    }
    #pragma unroll
    for (int it = 0; it < 2; it++) {
        int idx = it * 256 + tid;
        int r = idx >> 4, c16 = idx & 15;
        cp16(sb + 10240 + r * PBB + c16 * 16, Bh + (size_t)r * N + c16 * 8);
    }
}

// EPI: 0 plain fp32 | 1 bias+relu -> fp16 | 2 bias -> fp32 | 3 plain -> fp16
template<int EPI>
__global__ __launch_bounds__(256, 2)
void hgemm4_kernel(int M, int N, int K,
                   const __half* __restrict__ Ah,
                   const __half* __restrict__ Bh,
                   const float* __restrict__ bias,
                   float* __restrict__ C,
                   __half* __restrict__ Ch)
{
    extern __shared__ __align__(16) char smem[];
    uint32_t sb = (uint32_t)__cvta_generic_to_shared(smem);

    int tid  = threadIdx.x;
    int lane = tid & 31;
    int warp = tid >> 5;
    int wm = warp & 1;
    int wn = warp >> 1;
    int row0 = blockIdx.y * 128;
    int col0 = blockIdx.x * 128;

    const __half* Ahb = Ah + (size_t)row0 * K;
    const __half* Bhb = Bh + col0;

    float acc[4][4][4];
    #pragma unroll
    for (int i = 0; i < 4; i++)
        #pragma unroll
        for (int j = 0; j < 4; j++)
            #pragma unroll
            for (int c = 0; c < 4; c++) acc[i][j][c] = 0.f;

    int NT = K / 32;

    #pragma unroll
    for (int i = 0; i < NST - 1; i++) {
        load_stage(sb + i * STG3, Ahb + i * 32, Bhb + (size_t)(i * 32) * N, K, N, tid);
        CP_COMMIT();
    }

    for (int kt = 0; kt < NT; kt++) {
        CP_WAIT1();
        __syncthreads();

        int nk = kt + NST - 1;
        if (nk < NT) {
            load_stage(sb + (nk % NST) * STG3, Ahb + nk * 32,
                       Bhb + (size_t)(nk * 32) * N, K, N, tid);
        }
        CP_COMMIT();

        uint32_t st = sb + (kt % NST) * STG3;
        #pragma unroll
        for (int kk = 0; kk < 32; kk += 16) {
            uint32_t ahi[4][4], bfr[4][2];

            #pragma unroll
            for (int mi = 0; mi < 4; mi++) {
                int r = wm * 64 + mi * 16 + (lane & 15);
                int c = kk + (lane >> 4) * 8;
                LDSM_X4(ahi[mi][0], ahi[mi][1], ahi[mi][2], ahi[mi][3], st + r * PAB + c * 2);
            }
            #pragma unroll
            for (int nb2 = 0; nb2 < 2; nb2++) {
                int r = kk + (lane & 15);
                int c = wn * 32 + nb2 * 16 + (lane >> 4) * 8;
                uint32_t bh = st + 10240 + r * PBB + c * 2;
                LDSM_X4_T(bfr[nb2*2][0], bfr[nb2*2][1], bfr[nb2*2+1][0], bfr[nb2*2+1][1], bh);
            }

            #pragma unroll
            for (int mi = 0; mi < 4; mi++)
                #pragma unroll
                for (int ni = 0; ni < 4; ni++)
                    MMAH(acc[mi][ni], ahi[mi][0], ahi[mi][1], ahi[mi][2], ahi[mi][3],
                         bfr[ni][0], bfr[ni][1]);
        }
    }

    // epilogue
    int g = lane >> 2, t = lane & 3;
    #pragma unroll
    for (int mi = 0; mi < 4; mi++) {
        #pragma unroll
        for (int ni = 0; ni < 4; ni++) {
            int r = row0 + wm * 64 + mi * 16 + g;
            int c = col0 + wn * 32 + ni * 8 + t * 2;
            float v0 = acc[mi][ni][0], v1 = acc[mi][ni][1];
            float v2 = acc[mi][ni][2], v3 = acc[mi][ni][3];

            if (EPI == 1 || EPI == 2) {
                float bz0 = bias[c], bz1 = bias[c + 1];
                v0 += bz0; v1 += bz1; v2 += bz0; v3 += bz1;
            }
            if (EPI == 1) {
                v0 = fmaxf(v0, 0.f); v1 = fmaxf(v1, 0.f);
                v2 = fmaxf(v2, 0.f); v3 = fmaxf(v3, 0.f);
            }

            if (EPI == 0 || EPI == 2) {
                *(float2*)&C[(size_t)r * N + c]       = make_float2(v0, v1);
                *(float2*)&C[(size_t)(r + 8) * N + c] = make_float2(v2, v3);
            } else {
                *(uint32_t*)&Ch[(size_t)r * N + c]       = pack_h2(v0, v1);
                *(uint32_t*)&Ch[(size_t)(r + 8) * N + c] = pack_h2(v2, v3);
            }
        }
    }
}

// ---------------- flash attention: fp16 single-term, cp.async ----------------
// QKV input fused layout [NR, 3*DD]; Q at col 0, K at DD, V at 2*DD.
// smem: Q staged once (9216 B), then two 18432B KV buffers (K +0, V +9216).
#define QKVS (3*DD)

__device__ __forceinline__ void load_kv(uint32_t buf,
                                        const __half* __restrict__ KhB,
                                        const __half* __restrict__ VhB,
                                        int k0, int tid)
{
    #pragma unroll
    for (int it = 0; it < 4; it++) {
        int idx = it * 128 + tid;
        int r = idx >> 3, c = idx & 7;
        cp16(buf + r * 144 + c * 16,        KhB + (size_t)(k0 + r) * QKVS + c * 8);
        cp16(buf + 9216 + r * 144 + c * 16, VhB + (size_t)(k0 + r) * QKVS + c * 8);
    }
}

__global__ __launch_bounds__(128)
void attn_f16_kernel(const __half* __restrict__ QKV,
                     const int* __restrict__ vlen,
                     __half* __restrict__ Oh)
{
    __shared__ __align__(16) char smem[36864];
    uint32_t sb = (uint32_t)__cvta_generic_to_shared(smem);

    int tid  = threadIdx.x;
    int lane = tid & 31;
    int warp = tid >> 5;
    int g    = lane >> 2;
    int t    = lane & 3;

    int bh = blockIdx.y;
    int b  = bh >> 4;
    int h  = bh & 15;
    int q0 = blockIdx.x * 64;
    int vl = vlen[b];

    size_t base = (size_t)(b * SS) * QKVS + h * HD;
    const __half* QhB = QKV + base + (size_t)q0 * QKVS;
    const __half* KhB = QKV + base + DD;
    const __half* VhB = QKV + base + 2 * DD;

    // stage Q
    #pragma unroll
    for (int it = 0; it < 4; it++) {
        int idx = it * 128 + tid;
        int r = idx >> 3, c = idx & 7;
        cp16(sb + r * 144 + c * 16, QhB + (size_t)r * QKVS + c * 8);
    }
    CP_COMMIT(); CP_WAIT0();
    __syncthreads();

    uint32_t qh[4][4];
    #pragma unroll
    for (int kk = 0; kk < 4; kk++) {
        int r = warp * 16 + (lane & 15);
        int c = kk * 16 + (lane >> 4) * 8;
        LDSM_X4(qh[kk][0], qh[kk][1], qh[kk][2], qh[kk][3], sb + r * 144 + c * 2);
    }
    __syncthreads();    // Q frags read; smem reusable for KV

    float o[8][4];
    #pragma unroll
    for (int i = 0; i < 8; i++)
        #pragma unroll
        for (int c = 0; c < 4; c++) o[i][c] = 0.f;
    float m0 = -1e30f, m1 = -1e30f, l0 = 0.f, l1 = 0.f;

    int nkt = (vl + 63) >> 6;

    load_kv(sb, KhB, VhB, 0, tid);
    CP_COMMIT();

    for (int kt = 0; kt < nkt; kt++) {
        __syncthreads();     // compute of kt-1 done before overwriting its buffer
        if (kt + 1 < nkt)
            load_kv(sb + ((kt + 1) & 1) * 18432, KhB, VhB, (kt + 1) * 64, tid);
        CP_COMMIT();
        CP_WAIT1();
        __syncthreads();     // tile kt resident for all warps

        uint32_t cur = sb + (kt & 1) * 18432;
        int k0 = kt * 64;

        // S = Q K^T
        float s[8][4];
        #pragma unroll
        for (int i = 0; i < 8; i++)
            #pragma unroll
            for (int c = 0; c < 4; c++) s[i][c] = 0.f;

        #pragma unroll
        for (int kk = 0; kk < 4; kk++) {
            #pragma unroll
            for (int nb = 0; nb < 4; nb++) {
                int r = nb * 16 + (lane & 15);
                int c = kk * 16 + (lane >> 4) * 8;
                uint32_t kh0, kh1, kh2, kh3;
                LDSM_X4(kh0, kh1, kh2, kh3, cur + r * 144 + c * 2);
                MMAH(s[2*nb],   qh[kk][0], qh[kk][1], qh[kk][2], qh[kk][3], kh0, kh2);
                MMAH(s[2*nb+1], qh[kk][0], qh[kk][1], qh[kk][2], qh[kk][3], kh1, kh3);
            }
        }

        // scale + mask
        #pragma unroll
        for (int nb = 0; nb < 8; nb++) {
            int c0 = k0 + nb * 8 + 2 * t;
            int c1 = c0 + 1;
            s[nb][0] = (c0 < vl) ? s[nb][0] * 0.125f : -1e30f;
            s[nb][1] = (c1 < vl) ? s[nb][1] * 0.125f : -1e30f;
            s[nb][2] = (c0 < vl) ? s[nb][2] * 0.125f : -1e30f;
            s[nb][3] = (c1 < vl) ? s[nb][3] * 0.125f : -1e30f;
        }

        float tm0 = -1e30f, tm1 = -1e30f;
        #pragma unroll
        for (int nb = 0; nb < 8; nb++) {
            tm0 = fmaxf(tm0, fmaxf(s[nb][0], s[nb][1]));
            tm1 = fmaxf(tm1, fmaxf(s[nb][2], s[nb][3]));
        }
        tm0 = fmaxf(tm0, __shfl_xor_sync(0xffffffffu, tm0, 1));
        tm0 = fmaxf(tm0, __shfl_xor_sync(0xffffffffu, tm0, 2));
        tm1 = fmaxf(tm1, __shfl_xor_sync(0xffffffffu, tm1, 1));
        tm1 = fmaxf(tm1, __shfl_xor_sync(0xffffffffu, tm1, 2));

        float mn0 = fmaxf(m0, tm0);
        float mn1 = fmaxf(m1, tm1);
        float al0 = expf_fast(m0 - mn0);
        float al1 = expf_fast(m1 - mn1);

        uint32_t pA[4][4];
        float ls0 = 0.f, ls1 = 0.f;
        #pragma unroll
        for (int nb = 0; nb < 8; nb++) {
            float p0 = expf_fast(s[nb][0] - mn0);
            float p1 = expf_fast(s[nb][1] - mn0);
            float p2 = expf_fast(s[nb][2] - mn1);
            float p3 = expf_fast(s[nb][3] - mn1);
            ls0 += p0 + p1;
            ls1 += p2 + p3;
            int ks = nb >> 1;
            int hf = (nb & 1) * 2;
            pA[ks][hf + 0] = pack_h2(p0, p1);
            pA[ks][hf + 1] = pack_h2(p2, p3);
        }
        ls0 += __shfl_xor_sync(0xffffffffu, ls0, 1);
        ls0 += __shfl_xor_sync(0xffffffffu, ls0, 2);
        ls1 += __shfl_xor_sync(0xffffffffu, ls1, 1);
        ls1 += __shfl_xor_sync(0xffffffffu, ls1, 2);

        l0 = l0 * al0 + ls0;
        l1 = l1 * al1 + ls1;
        m0 = mn0;
        m1 = mn1;

        #pragma unroll
        for (int nb = 0; nb < 8; nb++) {
            o[nb][0] *= al0; o[nb][1] *= al0;
            o[nb][2] *= al1; o[nb][3] *= al1;
        }

        // O += P V
        #pragma unroll
        for (int kk = 0; kk < 4; kk++) {
            uint32_t a0 = pA[kk][0], a1 = pA[kk][1], a2 = pA[kk][2], a3 = pA[kk][3];
            #pragma unroll
            for (int nb = 0; nb < 4; nb++) {
                int r = kk * 16 + (lane & 15);
                int c = nb * 16 + (lane >> 4) * 8;
                uint32_t vh0, vh1, vh2, vh3;
                LDSM_X4_T(vh0, vh1, vh2, vh3, cur + 9216 + r * 144 + c * 2);
                MMAH(o[2*nb],   a0, a1, a2, a3, vh0, vh1);
                MMAH(o[2*nb+1], a0, a1, a2, a3, vh2, vh3);
            }
        }
    }

    float inv0 = 1.f / l0;
    float inv1 = 1.f / l1;
    int row0g = q0 + warp * 16 + g;
    int row1g = row0g + 8;
    __half* Ohb = Oh + (size_t)(b * SS) * DD + h * HD;
    #pragma unroll
    for (int nb = 0; nb < 8; nb++) {
        int col = nb * 8 + 2 * t;
        *(uint32_t*)(Ohb + (size_t)row0g * DD + col) =
            pack_h2(o[nb][0] * inv0, o[nb][1] * inv0);
        *(uint32_t*)(Ohb + (size_t)row1g * DD + col) =
            pack_h2(o[nb][2] * inv1, o[nb][3] * inv1);
    }
}

// ---------------- fused residual + LayerNorm --------------------------------
template<int SPLIT>
__global__ __launch_bounds__(256)
void ln_kernel(const float* __restrict__ A,
               const float* __restrict__ R,
               const float* __restrict__ g,
               const float* __restrict__ be,
               float* __restrict__ out,
               __half* __restrict__ oh)
{
    int row = blockIdx.x;
    int t   = threadIdx.x;
    const float4* a4 = (const float4*)(A + (size_t)row * DD);
    const float4* r4 = (const float4*)(R + (size_t)row * DD);
    float4 av = a4[t];
    float4 rv = r4[t];
    float x0 = av.x + rv.x, x1 = av.y + rv.y, x2 = av.z + rv.z, x3 = av.w + rv.w;

    float s = x0 + x1 + x2 + x3;
    float q = x0 * x0 + x1 * x1 + x2 * x2 + x3 * x3;
    #pragma unroll
    for (int off = 16; off >= 1; off >>= 1) {
        s += __shfl_xor_sync(0xffffffffu, s, off);
        q += __shfl_xor_sync(0xffffffffu, q, off);
    }
    __shared__ float rs[8], rq[8];
    int w = t >> 5, lane = t & 31;
    if (lane == 0) { rs[w] = s; rq[w] = q; }
    __syncthreads();
    float tot = 0.f, totq = 0.f;
    #pragma unroll
    for (int i = 0; i < 8; i++) { tot += rs[i]; totq += rq[i]; }

    float mean = tot * (1.f / DD);
    float var  = totq * (1.f / DD) - mean * mean;
    float rstd = rsqrtf(var + EPSL);

    float4 gv = ((const float4*)g)[t];
    float4 bv = ((const float4*)be)[t];
    float4 ov;
    ov.x = (x0 - mean) * rstd * gv.x + bv.x;
    ov.y = (x1 - mean) * rstd * gv.y + bv.y;
    ov.z = (x2 - mean) * rstd * gv.z + bv.z;
    ov.w = (x3 - mean) * rstd * gv.w + bv.w;
    ((float4*)(out + (size_t)row * DD))[t] = ov;

    if (SPLIT) {
        uint2 uh;
        __half* hp = (__half*)&uh;
        hp[0] = __float2half_rn(ov.x);
        hp[1] = __float2half_rn(ov.y);
        hp[2] = __float2half_rn(ov.z);
        hp[3] = __float2half_rn(ov.w);
        ((uint2*)(oh + (size_t)row * DD))[t] = uh;
    }
}

// ---------------- launch ----------------------------------------------------
extern "C" void kernel_launch(void* const* d_in, const int* in_sizes, int n_in,
                              void* d_out, int out_size)
{
    const float* x   = (const float*)d_in[0];
    const int*   vl  = (const int*)  d_in[1];
    const float* Wq  = (const float*)d_in[2];
    const float* Wk  = (const float*)d_in[3];
    const float* Wv  = (const float*)d_in[4];
    const float* Wo  = (const float*)d_in[5];
    const float* W1  = (const float*)d_in[6];
    const float* b1  = (const float*)d_in[7];
    const float* W2  = (const float*)d_in[8];
    const float* b2  = (const float*)d_in[9];
    const float* g1  = (const float*)d_in[10];
    const float* be1 = (const float*)d_in[11];
    const float* g2  = (const float*)d_in[12];
    const float* be2 = (const float*)d_in[13];
    float* out = (float*)d_out;

    float *q, *k, *r;
    cudaGetSymbolAddress((void**)&q, g_q);
    cudaGetSymbolAddress((void**)&k, g_k);
    cudaGetSymbolAddress((void**)&r, g_r);

    __half *xh, *qkv, *ah, *rh, *ffh;
    cudaGetSymbolAddress((void**)&xh,  g_xh);
    cudaGetSymbolAddress((void**)&qkv, g_qkv);
    cudaGetSymbolAddress((void**)&ah,  g_ah);
    cudaGetSymbolAddress((void**)&rh,  g_rh);
    cudaGetSymbolAddress((void**)&ffh, g_ffh);

    __half *wqkv, *wo, *w1, *w2;
    cudaGetSymbolAddress((void**)&wqkv, g_wqkv);
    cudaGetSymbolAddress((void**)&wo, g_wo);
    cudaGetSymbolAddress((void**)&w1, g_w1);
    cudaGetSymbolAddress((void**)&w2, g_w2);

    int gemm_smem = NST * STG3;   // 56832
    cudaFuncSetAttribute(hgemm4_kernel<0>, cudaFuncAttributeMaxDynamicSharedMemorySize, gemm_smem);
    cudaFuncSetAttribute(hgemm4_kernel<1>, cudaFuncAttributeMaxDynamicSharedMemorySize, gemm_smem);
    cudaFuncSetAttribute(hgemm4_kernel<2>, cudaFuncAttributeMaxDynamicSharedMemorySize, gemm_smem);
    cudaFuncSetAttribute(hgemm4_kernel<3>, cudaFuncAttributeMaxDynamicSharedMemorySize, gemm_smem);

    // one-shot fp16 conversion of weights + input
    SplitArgs sa;
    sa.s[0] = {Wq, wqkv, DD*DD/1024, DD, 3*DD, 0};
    sa.s[1] = {Wk, wqkv, DD*DD/1024, DD, 3*DD, DD};
    sa.s[2] = {Wv, wqkv, DD*DD/1024, DD, 3*DD, 2*DD};
    sa.s[3] = {Wo, wo,   DD*DD/1024, DD, DD,  0};
    sa.s[4] = {W1, w1,   DD*FF/1024, FF, FF,  0};
    sa.s[5] = {W2, w2,   DD*FF/1024, DD, DD,  0};
    sa.s[6] = {x,  xh,   NR*DD/1024, DD, DD,  0};
    int nblk = 0;
    for (int i = 0; i < 7; i++) nblk += sa.s[i].nblk;
    split_all_kernel<<<nblk, 256>>>(sa);

    dim3 gQKV(3 * DD / 128, NR / 128);   // (24, 64)
    dim3 gD(DD / 128, NR / 128);         // (8, 64)
    dim3 gF(FF / 128, NR / 128);         // (32, 64)

    // fused QKV projection -> fp16 [NR, 3*DD]
    hgemm4_kernel<3><<<gQKV, 256, gemm_smem>>>(NR, 3 * DD, DD, xh, wqkv,
                                               nullptr, nullptr, qkv);

    // attention -> fp16 [NR, DD]
    attn_f16_kernel<<<dim3(SS / 64, BB * HH), 128>>>(qkv, vl, ah);

    // output projection -> q fp32
    hgemm4_kernel<0><<<gD, 256, gemm_smem>>>(NR, DD, DD, ah, wo,
                                             nullptr, q, nullptr);

    // residual + LN1 -> r fp32 + rh fp16
    ln_kernel<1><<<NR, 256>>>(q, x, g1, be1, r, rh);

    // FFN
    hgemm4_kernel<1><<<gF, 256, gemm_smem>>>(NR, FF, DD, rh, w1, b1, nullptr, ffh);
    hgemm4_kernel<2><<<gD, 256, gemm_smem>>>(NR, DD, FF, ffh, w2, b2, k, nullptr);

    // residual + LN2 -> output
    ln_kernel<0><<<NR, 256>>>(k, r, g2, be2, out, nullptr);
}